// round 12
// baseline (speedup 1.0000x reference)
#include <cuda_runtime.h>
#include <cuda_bf16.h>
#include <cstdint>

#define NB 8
#define NS 2048
#define NF 256
#define NE 64
#define NDK 256
#define NIN 384

__device__ __forceinline__ void mma_bf16(float d[4], const uint32_t a[4],
                                         uint32_t b0, uint32_t b1) {
    asm volatile(
        "mma.sync.aligned.m16n8k16.row.col.f32.bf16.bf16.f32 "
        "{%0,%1,%2,%3}, {%4,%5,%6,%7}, {%8,%9}, {%0,%1,%2,%3};"
        : "+f"(d[0]), "+f"(d[1]), "+f"(d[2]), "+f"(d[3])
        : "r"(a[0]), "r"(a[1]), "r"(a[2]), "r"(a[3]), "r"(b0), "r"(b1));
}

// ldmatrix.x4: lane addr = row base + (lane&15)*stride + (lane>>4)*16B.
// Returns r0=(rows0-7,k0-7) r1=(rows8-15,k0-7) r2=(rows0-7,k8-15) r3=(rows8-15,k8-15).
// For A fragments: (a0,a1,a2,a3) = (r0,r1,r2,r3).
// For B fragments: n-tile low = (r0,r2), n-tile high = (r1,r3).
__device__ __forceinline__ void ldmx4(uint32_t r[4], uint32_t addr) {
    asm volatile("ldmatrix.sync.aligned.m8n8.x4.shared.b16 {%0,%1,%2,%3}, [%4];"
        : "=r"(r[0]), "=r"(r[1]), "=r"(r[2]), "=r"(r[3]) : "r"(addr));
}

__device__ __forceinline__ uint32_t pack_hi2(float a, float b, uint32_t& lo) {
    __nv_bfloat162 h, l;
    h.x = __float2bfloat16_rn(a); h.y = __float2bfloat16_rn(b);
    l.x = __float2bfloat16_rn(a - __bfloat162float(h.x));
    l.y = __float2bfloat16_rn(b - __bfloat162float(h.y));
    lo = *(uint32_t*)&l;
    return *(uint32_t*)&h;
}

__device__ __forceinline__ uint32_t smem_u32(const void* p) {
    uint32_t a;
    asm("{ .reg .u64 t; cvta.to.shared.u64 t, %1; cvt.u32.u64 %0, t; }"
        : "=r"(a) : "l"(p));
    return a;
}

#define CP16(dst, src) \
    asm volatile("cp.async.cg.shared.global [%0], [%1], 16;" \
                 :: "r"(dst), "l"(src))
#define CP_COMMIT()   asm volatile("cp.async.commit_group;" ::: "memory")
#define CP_WAIT_ALL() asm volatile("cp.async.wait_all;" ::: "memory")

// ---------------------------------------------------------------------------
// Global scratch (bf16 hi/lo splits)
// ---------------------------------------------------------------------------
__device__ __nv_bfloat16 g_qh[(size_t)NB * NS * NDK];
__device__ __nv_bfloat16 g_ql[(size_t)NB * NS * NDK];
__device__ __nv_bfloat16 g_kh[(size_t)NB * NS * NDK];
__device__ __nv_bfloat16 g_kl[(size_t)NB * NS * NDK];
__device__ __nv_bfloat16 g_vth[(size_t)NB * NF * NS];  // [b][f][s]
__device__ __nv_bfloat16 g_vtl[(size_t)NB * NF * NS];

// ---------------------------------------------------------------------------
// Kernel 1: Q/K projection via bf16-split HMMA + ldmatrix fragments.
// K chunk = 64 (6 chunks) -> smem 72KB -> 2 CTAs/SM.
// ---------------------------------------------------------------------------
#define XW      36       /* words per staged row (64 bf16 + 8 pad) */
#define XROW_B  (XW * 4) /* 144 bytes */
#define XH_OFF  0
#define XL_OFF  18432
#define WH_OFF  36864
#define WL_OFF  55296
#define PSMEM   73728

__global__ __launch_bounds__(256, 2) void proj_mma(
    const float* __restrict__ seq, const float* __restrict__ pos,
    const float* __restrict__ tim, const float* __restrict__ Wq,
    const float* __restrict__ Wk)
{
    extern __shared__ char smem[];
    const uint32_t sb = smem_u32(smem);
    const int tid = threadIdx.x, wid = tid >> 5, lane = tid & 31;
    const int wr = wid & 3, wc = wid >> 2;
    const int g = lane >> 2, t4 = lane & 3;
    const int m0 = blockIdx.x * 128, n0 = blockIdx.y * 128;
    const float* W = blockIdx.z ? Wk : Wq;
    __nv_bfloat16* dh = blockIdx.z ? g_kh : g_qh;
    __nv_bfloat16* dl = blockIdx.z ? g_kl : g_ql;

    uint32_t* Xh = (uint32_t*)(smem + XH_OFF);
    uint32_t* Xl = (uint32_t*)(smem + XL_OFF);
    uint32_t* Wh = (uint32_t*)(smem + WH_OFF);
    uint32_t* Wl = (uint32_t*)(smem + WL_OFF);

    // ldmatrix per-lane addresses
    const uint32_t lrow = (uint32_t)(lane & 15) * XROW_B + (uint32_t)((lane >> 4) << 4);
    const uint32_t xa = sb + XH_OFF + (uint32_t)(32 * wr) * XROW_B + lrow;  // + mi*16 rows
    const uint32_t wa = sb + WH_OFF + (uint32_t)(64 * wc) * XROW_B + lrow;  // + jnp*16 rows

    float acc[2][8][4];
#pragma unroll
    for (int mi = 0; mi < 2; ++mi)
#pragma unroll
        for (int jn = 0; jn < 8; ++jn)
#pragma unroll
            for (int u = 0; u < 4; ++u) acc[mi][jn][u] = 0.f;

    for (int ch = 0; ch < 6; ++ch) {
        const float* xsrc; int xw, xcol;
        if (ch < 4)      { xsrc = seq; xw = NF; xcol = ch * 64; }
        else if (ch < 5) { xsrc = pos; xw = NE; xcol = 0; }
        else             { xsrc = tim; xw = NE; xcol = 0; }
        const int wcol = ch * 64;

        __syncthreads();
        for (int i = tid; i < 2048; i += 256) {
            int row = i >> 4, cc = (i & 15) * 4;
            float4 xv = *(const float4*)(xsrc + (size_t)(m0 + row) * xw + xcol + cc);
            uint32_t l0, l1;
            uint32_t h0 = pack_hi2(xv.x, xv.y, l0);
            uint32_t h1 = pack_hi2(xv.z, xv.w, l1);
            int w = row * XW + (cc >> 1);
            *(uint2*)(Xh + w) = make_uint2(h0, h1);
            *(uint2*)(Xl + w) = make_uint2(l0, l1);

            float4 wv = *(const float4*)(W + (size_t)(n0 + row) * NIN + wcol + cc);
            uint32_t wl0, wl1;
            uint32_t wh0 = pack_hi2(wv.x, wv.y, wl0);
            uint32_t wh1 = pack_hi2(wv.z, wv.w, wl1);
            *(uint2*)(Wh + w) = make_uint2(wh0, wh1);
            *(uint2*)(Wl + w) = make_uint2(wl0, wl1);
        }
        __syncthreads();

#pragma unroll
        for (int ks = 0; ks < 4; ++ks) {
            const uint32_t ko = (uint32_t)ks * 32;
            uint32_t ah[2][4], al[2][4];
#pragma unroll
            for (int mi = 0; mi < 2; ++mi) {
                ldmx4(ah[mi], xa + (uint32_t)(mi * 16) * XROW_B + ko);
                ldmx4(al[mi], xa + (XL_OFF - XH_OFF) + (uint32_t)(mi * 16) * XROW_B + ko);
            }
#pragma unroll
            for (int jnp = 0; jnp < 4; ++jnp) {
                uint32_t bh[4], bl[4];
                ldmx4(bh, wa + (uint32_t)(jnp * 16) * XROW_B + ko);
                ldmx4(bl, wa + (WL_OFF - WH_OFF) + (uint32_t)(jnp * 16) * XROW_B + ko);
#pragma unroll
                for (int mi = 0; mi < 2; ++mi) {
                    mma_bf16(acc[mi][2 * jnp],     ah[mi], bh[0], bh[2]);
                    mma_bf16(acc[mi][2 * jnp],     al[mi], bh[0], bh[2]);
                    mma_bf16(acc[mi][2 * jnp],     ah[mi], bl[0], bl[2]);
                    mma_bf16(acc[mi][2 * jnp + 1], ah[mi], bh[1], bh[3]);
                    mma_bf16(acc[mi][2 * jnp + 1], al[mi], bh[1], bh[3]);
                    mma_bf16(acc[mi][2 * jnp + 1], ah[mi], bl[1], bl[3]);
                }
            }
        }
    }

#pragma unroll
    for (int mi = 0; mi < 2; ++mi) {
        int m1 = m0 + 32 * wr + 16 * mi + g;
        int m2 = m1 + 8;
#pragma unroll
        for (int jn = 0; jn < 8; ++jn) {
            int n = n0 + 64 * wc + 8 * jn + 2 * t4;
            uint32_t lo1, lo2;
            uint32_t hi1 = pack_hi2(acc[mi][jn][0], acc[mi][jn][1], lo1);
            uint32_t hi2 = pack_hi2(acc[mi][jn][2], acc[mi][jn][3], lo2);
            *(uint32_t*)(dh + (size_t)m1 * NDK + n) = hi1;
            *(uint32_t*)(dl + (size_t)m1 * NDK + n) = lo1;
            *(uint32_t*)(dh + (size_t)m2 * NDK + n) = hi2;
            *(uint32_t*)(dl + (size_t)m2 * NDK + n) = lo2;
        }
    }
}

// ---------------------------------------------------------------------------
// Kernel 2: V = seq transpose + bf16 split: g_vt{h,l}[b][f][s]
// ---------------------------------------------------------------------------
__global__ __launch_bounds__(256) void vsplit_kernel(const float* __restrict__ seq)
{
    __shared__ float t[32][33];
    const int b = blockIdx.z, s0 = blockIdx.x * 32, f0 = blockIdx.y * 32;
    const int tx = threadIdx.x, ty = threadIdx.y;
#pragma unroll
    for (int r = 0; r < 4; ++r) {
        int sl = ty + r * 8;
        t[sl][tx] = seq[((size_t)b * NS + s0 + sl) * NF + f0 + tx];
    }
    __syncthreads();
#pragma unroll
    for (int r = 0; r < 4; ++r) {
        int fl = ty + r * 8;
        float v = t[tx][fl];
        __nv_bfloat16 h = __float2bfloat16_rn(v);
        float l = v - __bfloat162float(h);
        size_t idx = ((size_t)b * NF + f0 + fl) * NS + s0 + tx;
        g_vth[idx] = h;
        g_vtl[idx] = __float2bfloat16_rn(l);
    }
}

// ---------------------------------------------------------------------------
// Kernel 3: mma.sync (bf16 HMMA) fused attention, cp.async + ldmatrix.
// ---------------------------------------------------------------------------
#define QKW      132   /* uint32 words per Q/K row: (256+8 pad) bf16 */
#define VPW      36    /* uint32 words per VT/P row: (64+8 pad) bf16 */
#define QROW_B   (QKW * 4)  /* 528 */
#define VROW_B   (VPW * 4)  /* 144 */
#define QH_OFF   0
#define QL_OFF   33792
#define KH_OFF   67584
#define KL_OFF   101376
#define VTH_OFF  135168
#define VTL_OFF  172032
#define PH_OFF   208896
#define PL_OFF   218112
#define DEN_OFF  227328
#define ASMEM    227840

__global__ __launch_bounds__(256, 1) void attn_mma(
    const float* __restrict__ cmask,
    const int*   __restrict__ causality,
    float* __restrict__ out)
{
    extern __shared__ char smem[];
    const uint32_t sb = smem_u32(smem);
    const int tid = threadIdx.x;
    const int wid = tid >> 5, lane = tid & 31;
    const int wr = wid & 3, wc = wid >> 2;   // q-band, f-half
    const int g = lane >> 2, t4 = lane & 3;  // fragment row, quad index
    const int b = blockIdx.y;
    const int causal = causality[0];

    float* den_s = (float*)(smem + DEN_OFF);

    // ldmatrix per-lane addresses
    const uint32_t lq = (uint32_t)(lane & 15) * QROW_B + (uint32_t)((lane >> 4) << 4);
    const uint32_t lv = (uint32_t)(lane & 15) * VROW_B + (uint32_t)((lane >> 4) << 4);
    const uint32_t qah = sb + QH_OFF + (uint32_t)(16 * wr) * QROW_B + lq;
    const uint32_t qal = qah + (QL_OFF - QH_OFF);
    const uint32_t kah = sb + KH_OFF + (uint32_t)(32 * wc) * QROW_B + lq;  // + jp*16 rows
    const uint32_t pah = sb + PH_OFF + (uint32_t)(16 * wr) * VROW_B + lv;
    const uint32_t pal = pah + (PL_OFF - PH_OFF);
    const uint32_t vah = sb + VTH_OFF + (uint32_t)(128 * wc) * VROW_B + lv; // + jp*16 rows

    auto stage_K = [&](int k0) {
        const __nv_bfloat16* kh = g_kh + ((size_t)b * NS + k0) * NDK;
        const __nv_bfloat16* kl = g_kl + ((size_t)b * NS + k0) * NDK;
        for (int i = tid; i < 2048; i += 256) {
            int row = i >> 5, c8 = (i & 31) << 3;
            uint32_t off = (uint32_t)(row * (QKW * 2) + c8) * 2;
            CP16(sb + KH_OFF + off, kh + (size_t)row * NDK + c8);
            CP16(sb + KL_OFF + off, kl + (size_t)row * NDK + c8);
        }
    };
    auto stage_V = [&](int k0) {
        const __nv_bfloat16* vh = g_vth + (size_t)b * NF * NS + k0;
        const __nv_bfloat16* vl = g_vtl + (size_t)b * NF * NS + k0;
        for (int i = tid; i < 2048; i += 256) {
            int f = i >> 3, k8 = (i & 7) << 3;
            uint32_t off = (uint32_t)(f * (VPW * 2) + k8) * 2;
            CP16(sb + VTH_OFF + off, vh + (size_t)f * NS + k8);
            CP16(sb + VTL_OFF + off, vl + (size_t)f * NS + k8);
        }
    };

    for (int half = 0; half < 2; ++half) {
        const int qt = half ? (31 - (int)blockIdx.x) : (int)blockIdx.x;
        const int q0 = qt * 64;

        __syncthreads();  // previous half fully done before Q restage

        {
            const __nv_bfloat16* qh = g_qh + ((size_t)b * NS + q0) * NDK;
            const __nv_bfloat16* ql = g_ql + ((size_t)b * NS + q0) * NDK;
            for (int i = tid; i < 2048; i += 256) {
                int row = i >> 5, c8 = (i & 31) << 3;
                uint32_t off = (uint32_t)(row * (QKW * 2) + c8) * 2;
                *(uint4*)(smem + QH_OFF + off) = *(const uint4*)(qh + (size_t)row * NDK + c8);
                *(uint4*)(smem + QL_OFF + off) = *(const uint4*)(ql + (size_t)row * NDK + c8);
            }
        }

        float o[16][4];
#pragma unroll
        for (int j = 0; j < 16; ++j)
#pragma unroll
            for (int u = 0; u < 4; ++u) o[j][u] = 0.f;
        float denA = 0.f, denB = 0.f;

        const int kt0 = causal ? qt : 0;

        stage_K(kt0 * 64);
        stage_V(kt0 * 64);
        CP_COMMIT();

        for (int kt = kt0; kt < 32; ++kt) {
            const int k0 = kt * 64;

            // mask bits (overlaps in-flight cp.async)
            uint32_t mbits = 0;
            {
                const int q1 = q0 + 16 * wr + g;
                const int q2 = q1 + 8;
                const int kbase = k0 + 32 * wc + 2 * t4;
                const float* m1p = cmask + ((size_t)b * NS + q1) * NS;
                const float* m2p = cmask + ((size_t)b * NS + q2) * NS;
#pragma unroll
                for (int j = 0; j < 4; ++j) {
                    int kg = kbase + 8 * j;
                    float2 m1 = *(const float2*)(m1p + kg);
                    float2 m2 = *(const float2*)(m2p + kg);
                    uint32_t bits = 0;
                    if (m1.x > 0.f && (!causal || kg     >= q1)) bits |= 1u;
                    if (m1.y > 0.f && (!causal || kg + 1 >= q1)) bits |= 2u;
                    if (m2.x > 0.f && (!causal || kg     >= q2)) bits |= 4u;
                    if (m2.y > 0.f && (!causal || kg + 1 >= q2)) bits |= 8u;
                    mbits |= bits << (4 * j);
                }
            }

            CP_WAIT_ALL();
            __syncthreads();  // K/V (and Q on first iter) visible

            // ---- Phase A: S = Q K^T (3 bf16 splits), ldmatrix fragments
            float s[4][4];
#pragma unroll
            for (int j = 0; j < 4; ++j)
#pragma unroll
                for (int u = 0; u < 4; ++u) s[j][u] = 0.f;

#pragma unroll 4
            for (int ks = 0; ks < 16; ++ks) {
                const uint32_t ko = (uint32_t)ks * 32;
                uint32_t ah[4], al[4];
                ldmx4(ah, qah + ko);
                ldmx4(al, qal + ko);
#pragma unroll
                for (int jp = 0; jp < 2; ++jp) {
                    uint32_t bh[4], bl[4];
                    ldmx4(bh, kah + (uint32_t)(jp * 16) * QROW_B + ko);
                    ldmx4(bl, kah + (KL_OFF - KH_OFF) + (uint32_t)(jp * 16) * QROW_B + ko);
                    mma_bf16(s[2 * jp],     ah, bh[0], bh[2]);
                    mma_bf16(s[2 * jp],     al, bh[0], bh[2]);
                    mma_bf16(s[2 * jp],     ah, bl[0], bl[2]);
                    mma_bf16(s[2 * jp + 1], ah, bh[1], bh[3]);
                    mma_bf16(s[2 * jp + 1], al, bh[1], bh[3]);
                    mma_bf16(s[2 * jp + 1], ah, bl[1], bl[3]);
                }
            }

            // ---- epilogue: p = exp(min(s/16,10)) masked; den; P hi/lo -> SMEM
            {
#pragma unroll
                for (int j = 0; j < 4; ++j) {
                    uint32_t bb = mbits >> (4 * j);
                    float p0 = (bb & 1u) ? __expf(fminf(s[j][0] * 0.0625f, 10.f)) : 0.f;
                    float p1 = (bb & 2u) ? __expf(fminf(s[j][1] * 0.0625f, 10.f)) : 0.f;
                    float p2 = (bb & 4u) ? __expf(fminf(s[j][2] * 0.0625f, 10.f)) : 0.f;
                    float p3 = (bb & 8u) ? __expf(fminf(s[j][3] * 0.0625f, 10.f)) : 0.f;
                    denA += p0 + p1;
                    denB += p2 + p3;
                    uint32_t lo1, lo2;
                    uint32_t hi1 = pack_hi2(p0, p1, lo1);
                    uint32_t hi2 = pack_hi2(p2, p3, lo2);
                    int col = 32 * wc + 2 * t4 + 8 * j;
                    uint32_t w1 = (uint32_t)((16 * wr + g) * VPW + (col >> 1));
                    uint32_t w2 = (uint32_t)((16 * wr + g + 8) * VPW + (col >> 1));
                    ((uint32_t*)(smem + PH_OFF))[w1] = hi1;
                    ((uint32_t*)(smem + PL_OFF))[w1] = lo1;
                    ((uint32_t*)(smem + PH_OFF))[w2] = hi2;
                    ((uint32_t*)(smem + PL_OFF))[w2] = lo2;
                }
            }
            __syncthreads();  // P visible; all warps done with K (phase A)

            // prefetch next tile's K — overlaps all of phase B
            if (kt + 1 < 32) { stage_K(k0 + 64); CP_COMMIT(); }

            // ---- Phase B: O += P V^T (3 bf16 splits), ldmatrix fragments
#pragma unroll
            for (int ks = 0; ks < 4; ++ks) {
                const uint32_t ko = (uint32_t)ks * 32;
                uint32_t ah[4], al[4];
                ldmx4(ah, pah + ko);
                ldmx4(al, pal + ko);
#pragma unroll
                for (int jp = 0; jp < 8; ++jp) {
                    uint32_t bh[4], bl[4];
                    ldmx4(bh, vah + (uint32_t)(jp * 16) * VROW_B + ko);
                    ldmx4(bl, vah + (VTL_OFF - VTH_OFF) + (uint32_t)(jp * 16) * VROW_B + ko);
                    mma_bf16(o[2 * jp],     ah, bh[0], bh[2]);
                    mma_bf16(o[2 * jp],     al, bh[0], bh[2]);
                    mma_bf16(o[2 * jp],     ah, bl[0], bl[2]);
                    mma_bf16(o[2 * jp + 1], ah, bh[1], bh[3]);
                    mma_bf16(o[2 * jp + 1], al, bh[1], bh[3]);
                    mma_bf16(o[2 * jp + 1], ah, bl[1], bl[3]);
                }
            }
            __syncthreads();  // all warps done with V (phase B) and P

            // prefetch next tile's V — overlaps next tile's mask loads
            if (kt + 1 < 32) { stage_V(k0 + 64); CP_COMMIT(); }
        }

        denA += __shfl_xor_sync(0xffffffffu, denA, 1);
        denA += __shfl_xor_sync(0xffffffffu, denA, 2);
        denB += __shfl_xor_sync(0xffffffffu, denB, 1);
        denB += __shfl_xor_sync(0xffffffffu, denB, 2);
        __syncthreads();
        if (t4 == 0) {
            den_s[wc * 64 + 16 * wr + g] = denA;
            den_s[wc * 64 + 16 * wr + g + 8] = denB;
        }
        __syncthreads();

        {
            const int q1row = 16 * wr + g;
            const float inv1 = 1.0f / (den_s[q1row] + den_s[64 + q1row]);
            const float inv2 = 1.0f / (den_s[q1row + 8] + den_s[64 + q1row + 8]);
            float* o1 = out + ((size_t)b * NS + q0 + q1row) * NF;
            float* o2 = out + ((size_t)b * NS + q0 + q1row + 8) * NF;
#pragma unroll
            for (int j2 = 0; j2 < 16; ++j2) {
                int f = 128 * wc + 8 * j2 + 2 * t4;
                float2 v1, v2;
                v1.x = o[j2][0] * inv1; v1.y = o[j2][1] * inv1;
                v2.x = o[j2][2] * inv2; v2.y = o[j2][3] * inv2;
                *(float2*)(o1 + f) = v1;
                *(float2*)(o2 + f) = v2;
            }
        }
    }
}

// ---------------------------------------------------------------------------
extern "C" void kernel_launch(void* const* d_in, const int* in_sizes, int n_in,
                              void* d_out, int out_size)
{
    const float* seq  = (const float*)d_in[0];
    const float* pos  = (const float*)d_in[1];
    const float* tim  = (const float*)d_in[2];
    const float* Wq   = (const float*)d_in[3];
    const float* Wk   = (const float*)d_in[4];
    const float* cm   = (const float*)d_in[5];
    const int*   caus = (const int*)d_in[6];
    float* out = (float*)d_out;

    cudaFuncSetAttribute(proj_mma, cudaFuncAttributeMaxDynamicSharedMemorySize, PSMEM);
    cudaFuncSetAttribute(attn_mma, cudaFuncAttributeMaxDynamicSharedMemorySize, ASMEM);

    dim3 gp(NB * NS / 128, NDK / 128, 2);   // (128, 2, 2) = 512 CTAs
    proj_mma<<<gp, 256, PSMEM>>>(seq, pos, tim, Wq, Wk);

    dim3 gv(NS / 32, NF / 32, NB);
    vsplit_kernel<<<gv, dim3(32, 8)>>>(seq);

    dim3 ga(16, NB);   // 128 CTAs, 33 key-tiles each (causal), 1 wave
    attn_mma<<<ga, 256, ASMEM>>>(cm, caus, out);
}

// round 13
// speedup vs baseline: 1.1695x; 1.1695x over previous
#include <cuda_runtime.h>
#include <cuda_bf16.h>
#include <cuda_fp16.h>
#include <cstdint>

#define NB 8
#define NS 2048
#define NF 256
#define NE 64
#define NDK 256
#define NIN 384

__device__ __forceinline__ void mma_bf16(float d[4], const uint32_t a[4],
                                         uint32_t b0, uint32_t b1) {
    asm volatile(
        "mma.sync.aligned.m16n8k16.row.col.f32.bf16.bf16.f32 "
        "{%0,%1,%2,%3}, {%4,%5,%6,%7}, {%8,%9}, {%0,%1,%2,%3};"
        : "+f"(d[0]), "+f"(d[1]), "+f"(d[2]), "+f"(d[3])
        : "r"(a[0]), "r"(a[1]), "r"(a[2]), "r"(a[3]), "r"(b0), "r"(b1));
}
__device__ __forceinline__ void mma_f16(float d[4], const uint32_t a[4],
                                        uint32_t b0, uint32_t b1) {
    asm volatile(
        "mma.sync.aligned.m16n8k16.row.col.f32.f16.f16.f32 "
        "{%0,%1,%2,%3}, {%4,%5,%6,%7}, {%8,%9}, {%0,%1,%2,%3};"
        : "+f"(d[0]), "+f"(d[1]), "+f"(d[2]), "+f"(d[3])
        : "r"(a[0]), "r"(a[1]), "r"(a[2]), "r"(a[3]), "r"(b0), "r"(b1));
}

__device__ __forceinline__ uint32_t pack_hi2(float a, float b, uint32_t& lo) {
    __nv_bfloat162 h, l;
    h.x = __float2bfloat16_rn(a); h.y = __float2bfloat16_rn(b);
    l.x = __float2bfloat16_rn(a - __bfloat162float(h.x));
    l.y = __float2bfloat16_rn(b - __bfloat162float(h.y));
    lo = *(uint32_t*)&l;
    return *(uint32_t*)&h;
}

__device__ __forceinline__ uint32_t smem_u32(const void* p) {
    uint32_t a;
    asm("{ .reg .u64 t; cvta.to.shared.u64 t, %1; cvt.u32.u64 %0, t; }"
        : "=r"(a) : "l"(p));
    return a;
}

#define CP16(dst, src) \
    asm volatile("cp.async.cg.shared.global [%0], [%1], 16;" \
                 :: "r"(dst), "l"(src))
#define CP_COMMIT()   asm volatile("cp.async.commit_group;" ::: "memory")
#define CP_WAIT_ALL() asm volatile("cp.async.wait_all;" ::: "memory")

// ---------------------------------------------------------------------------
// Global scratch
// ---------------------------------------------------------------------------
__device__ __nv_bfloat16 g_qh[(size_t)NB * NS * NDK];
__device__ __nv_bfloat16 g_ql[(size_t)NB * NS * NDK];
__device__ __nv_bfloat16 g_kh[(size_t)NB * NS * NDK];
__device__ __nv_bfloat16 g_kl[(size_t)NB * NS * NDK];
__device__ __half        g_vt[(size_t)NB * NF * NS];   // [b][f][s], fp16 single

// ---------------------------------------------------------------------------
// Kernel 1: Q/K projection via bf16-split HMMA (R10 direct-LDS version).
// K chunk = 64 (6 chunks) -> smem 72KB -> 2 CTAs/SM.
// ---------------------------------------------------------------------------
#define XW      36
#define XH_OFF  0
#define XL_OFF  18432
#define WH_OFF  36864
#define WL_OFF  55296
#define PSMEM   73728

__global__ __launch_bounds__(256, 2) void proj_mma(
    const float* __restrict__ seq, const float* __restrict__ pos,
    const float* __restrict__ tim, const float* __restrict__ Wq,
    const float* __restrict__ Wk)
{
    extern __shared__ char smem[];
    const int tid = threadIdx.x, wid = tid >> 5, lane = tid & 31;
    const int wr = wid & 3, wc = wid >> 2;
    const int g = lane >> 2, t4 = lane & 3;
    const int m0 = blockIdx.x * 128, n0 = blockIdx.y * 128;
    const float* W = blockIdx.z ? Wk : Wq;
    __nv_bfloat16* dh = blockIdx.z ? g_kh : g_qh;
    __nv_bfloat16* dl = blockIdx.z ? g_kl : g_ql;

    uint32_t* Xh = (uint32_t*)(smem + XH_OFF);
    uint32_t* Xl = (uint32_t*)(smem + XL_OFF);
    uint32_t* Wh = (uint32_t*)(smem + WH_OFF);
    uint32_t* Wl = (uint32_t*)(smem + WL_OFF);

    float acc[2][8][4];
#pragma unroll
    for (int mi = 0; mi < 2; ++mi)
#pragma unroll
        for (int jn = 0; jn < 8; ++jn)
#pragma unroll
            for (int u = 0; u < 4; ++u) acc[mi][jn][u] = 0.f;

    for (int ch = 0; ch < 6; ++ch) {
        const float* xsrc; int xw, xcol;
        if (ch < 4)      { xsrc = seq; xw = NF; xcol = ch * 64; }
        else if (ch < 5) { xsrc = pos; xw = NE; xcol = 0; }
        else             { xsrc = tim; xw = NE; xcol = 0; }
        const int wcol = ch * 64;

        __syncthreads();
        for (int i = tid; i < 2048; i += 256) {
            int row = i >> 4, cc = (i & 15) * 4;
            float4 xv = *(const float4*)(xsrc + (size_t)(m0 + row) * xw + xcol + cc);
            uint32_t l0, l1;
            uint32_t h0 = pack_hi2(xv.x, xv.y, l0);
            uint32_t h1 = pack_hi2(xv.z, xv.w, l1);
            int w = row * XW + (cc >> 1);
            *(uint2*)(Xh + w) = make_uint2(h0, h1);
            *(uint2*)(Xl + w) = make_uint2(l0, l1);

            float4 wv = *(const float4*)(W + (size_t)(n0 + row) * NIN + wcol + cc);
            uint32_t wl0, wl1;
            uint32_t wh0 = pack_hi2(wv.x, wv.y, wl0);
            uint32_t wh1 = pack_hi2(wv.z, wv.w, wl1);
            *(uint2*)(Wh + w) = make_uint2(wh0, wh1);
            *(uint2*)(Wl + w) = make_uint2(wl0, wl1);
        }
        __syncthreads();

#pragma unroll
        for (int ks = 0; ks < 4; ++ks) {
            const int kw = ks * 8 + t4;
            uint32_t ah[2][4], al[2][4];
#pragma unroll
            for (int mi = 0; mi < 2; ++mi) {
                int r0 = (32 * wr + 16 * mi + g) * XW, r1 = r0 + 8 * XW;
                ah[mi][0] = Xh[r0 + kw];     ah[mi][1] = Xh[r1 + kw];
                ah[mi][2] = Xh[r0 + kw + 4]; ah[mi][3] = Xh[r1 + kw + 4];
                al[mi][0] = Xl[r0 + kw];     al[mi][1] = Xl[r1 + kw];
                al[mi][2] = Xl[r0 + kw + 4]; al[mi][3] = Xl[r1 + kw + 4];
            }
#pragma unroll
            for (int jn = 0; jn < 8; ++jn) {
                int br = (64 * wc + 8 * jn + g) * XW;
                uint32_t bh0 = Wh[br + kw], bh1 = Wh[br + kw + 4];
                uint32_t bl0 = Wl[br + kw], bl1 = Wl[br + kw + 4];
#pragma unroll
                for (int mi = 0; mi < 2; ++mi) {
                    mma_bf16(acc[mi][jn], ah[mi], bh0, bh1);
                    mma_bf16(acc[mi][jn], al[mi], bh0, bh1);
                    mma_bf16(acc[mi][jn], ah[mi], bl0, bl1);
                }
            }
        }
    }

#pragma unroll
    for (int mi = 0; mi < 2; ++mi) {
        int m1 = m0 + 32 * wr + 16 * mi + g;
        int m2 = m1 + 8;
#pragma unroll
        for (int jn = 0; jn < 8; ++jn) {
            int n = n0 + 64 * wc + 8 * jn + 2 * t4;
            uint32_t lo1, lo2;
            uint32_t hi1 = pack_hi2(acc[mi][jn][0], acc[mi][jn][1], lo1);
            uint32_t hi2 = pack_hi2(acc[mi][jn][2], acc[mi][jn][3], lo2);
            *(uint32_t*)(dh + (size_t)m1 * NDK + n) = hi1;
            *(uint32_t*)(dl + (size_t)m1 * NDK + n) = lo1;
            *(uint32_t*)(dh + (size_t)m2 * NDK + n) = hi2;
            *(uint32_t*)(dl + (size_t)m2 * NDK + n) = lo2;
        }
    }
}

// ---------------------------------------------------------------------------
// Kernel 2: V = seq transpose -> fp16 single: g_vt[b][f][s]
// ---------------------------------------------------------------------------
__global__ __launch_bounds__(256) void vsplit_kernel(const float* __restrict__ seq)
{
    __shared__ float t[32][33];
    const int b = blockIdx.z, s0 = blockIdx.x * 32, f0 = blockIdx.y * 32;
    const int tx = threadIdx.x, ty = threadIdx.y;
#pragma unroll
    for (int r = 0; r < 4; ++r) {
        int sl = ty + r * 8;
        t[sl][tx] = seq[((size_t)b * NS + s0 + sl) * NF + f0 + tx];
    }
    __syncthreads();
#pragma unroll
    for (int r = 0; r < 4; ++r) {
        int fl = ty + r * 8;
        float v = t[tx][fl];
        g_vt[((size_t)b * NF + f0 + fl) * NS + s0 + tx] = __float2half_rn(v);
    }
}

// ---------------------------------------------------------------------------
// Kernel 3: fused attention (R10 direct-LDS base).
// Phase A: QK^T bf16 3-term.  Phase B: PV fp16 2-term (Ph*Vh + Pl*Vh) —
// V single fp16, P split fp16 hi/lo (ph+pl == p nearly exactly; dropped
// term is p * (v - fp16(v)) ~ 2^-12 relative, incoherent -> ~1e-4 output).
// ---------------------------------------------------------------------------
#define QKW      132   /* uint32 words per Q/K row: (256+8 pad) bf16 */
#define VPW      36    /* uint32 words per VT/P row: (64+8 pad) f16 */
#define QH_OFF   0
#define QL_OFF   33792
#define KH_OFF   67584
#define KL_OFF   101376
#define VT_OFF   135168
#define PH_OFF   172032
#define PL_OFF   181248
#define DEN_OFF  190464
#define ASMEM    190976

__global__ __launch_bounds__(256, 1) void attn_mma(
    const float* __restrict__ cmask,
    const int*   __restrict__ causality,
    float* __restrict__ out)
{
    extern __shared__ char smem[];
    const uint32_t sb = smem_u32(smem);
    const int tid = threadIdx.x;
    const int wid = tid >> 5, lane = tid & 31;
    const int wr = wid & 3, wc = wid >> 2;   // q-band, f-half
    const int g = lane >> 2, t4 = lane & 3;  // fragment row, quad index
    const int b = blockIdx.y;
    const int causal = causality[0];

    const uint32_t* Qh32 = (const uint32_t*)(smem + QH_OFF);
    const uint32_t* Ql32 = (const uint32_t*)(smem + QL_OFF);
    const uint32_t* Kh32 = (const uint32_t*)(smem + KH_OFF);
    const uint32_t* Kl32 = (const uint32_t*)(smem + KL_OFF);
    const uint32_t* Vt32 = (const uint32_t*)(smem + VT_OFF);
    const uint32_t* Ph32 = (const uint32_t*)(smem + PH_OFF);
    const uint32_t* Pl32 = (const uint32_t*)(smem + PL_OFF);
    float* den_s = (float*)(smem + DEN_OFF);

    const int ar0 = (16 * wr + g) * QKW;
    const int ar1 = (16 * wr + g + 8) * QKW;
    const int pr0 = (16 * wr + g) * VPW;
    const int pr1 = (16 * wr + g + 8) * VPW;

    auto stage_K = [&](int k0) {
        const __nv_bfloat16* kh = g_kh + ((size_t)b * NS + k0) * NDK;
        const __nv_bfloat16* kl = g_kl + ((size_t)b * NS + k0) * NDK;
        for (int i = tid; i < 2048; i += 256) {
            int row = i >> 5, c8 = (i & 31) << 3;
            uint32_t off = (uint32_t)(row * (QKW * 2) + c8) * 2;
            CP16(sb + KH_OFF + off, kh + (size_t)row * NDK + c8);
            CP16(sb + KL_OFF + off, kl + (size_t)row * NDK + c8);
        }
    };
    auto stage_V = [&](int k0) {
        const __half* vh = g_vt + (size_t)b * NF * NS + k0;
        for (int i = tid; i < 2048; i += 256) {
            int f = i >> 3, k8 = (i & 7) << 3;
            uint32_t off = (uint32_t)(f * (VPW * 2) + k8) * 2;
            CP16(sb + VT_OFF + off, vh + (size_t)f * NS + k8);
        }
    };

    for (int half = 0; half < 2; ++half) {
        const int qt = half ? (31 - (int)blockIdx.x) : (int)blockIdx.x;
        const int q0 = qt * 64;

        __syncthreads();  // previous half fully done before Q restage

        {
            const __nv_bfloat16* qh = g_qh + ((size_t)b * NS + q0) * NDK;
            const __nv_bfloat16* ql = g_ql + ((size_t)b * NS + q0) * NDK;
            for (int i = tid; i < 2048; i += 256) {
                int row = i >> 5, c8 = (i & 31) << 3;
                uint32_t off = (uint32_t)(row * (QKW * 2) + c8) * 2;
                *(uint4*)(smem + QH_OFF + off) = *(const uint4*)(qh + (size_t)row * NDK + c8);
                *(uint4*)(smem + QL_OFF + off) = *(const uint4*)(ql + (size_t)row * NDK + c8);
            }
        }

        float o[16][4];
#pragma unroll
        for (int j = 0; j < 16; ++j)
#pragma unroll
            for (int u = 0; u < 4; ++u) o[j][u] = 0.f;
        float denA = 0.f, denB = 0.f;

        const int kt0 = causal ? qt : 0;

        stage_K(kt0 * 64);
        stage_V(kt0 * 64);
        CP_COMMIT();

        for (int kt = kt0; kt < 32; ++kt) {
            const int k0 = kt * 64;

            // mask bits (overlaps in-flight cp.async)
            uint32_t mbits = 0;
            {
                const int q1 = q0 + 16 * wr + g;
                const int q2 = q1 + 8;
                const int kbase = k0 + 32 * wc + 2 * t4;
                const float* m1p = cmask + ((size_t)b * NS + q1) * NS;
                const float* m2p = cmask + ((size_t)b * NS + q2) * NS;
#pragma unroll
                for (int j = 0; j < 4; ++j) {
                    int kg = kbase + 8 * j;
                    float2 m1 = *(const float2*)(m1p + kg);
                    float2 m2 = *(const float2*)(m2p + kg);
                    uint32_t bits = 0;
                    if (m1.x > 0.f && (!causal || kg     >= q1)) bits |= 1u;
                    if (m1.y > 0.f && (!causal || kg + 1 >= q1)) bits |= 2u;
                    if (m2.x > 0.f && (!causal || kg     >= q2)) bits |= 4u;
                    if (m2.y > 0.f && (!causal || kg + 1 >= q2)) bits |= 8u;
                    mbits |= bits << (4 * j);
                }
            }

            CP_WAIT_ALL();
            __syncthreads();  // K/V (and Q on first iter) visible

            // ---- Phase A: S = Q K^T (3 bf16 splits), direct-LDS fragments
            float s[4][4];
#pragma unroll
            for (int j = 0; j < 4; ++j)
#pragma unroll
                for (int u = 0; u < 4; ++u) s[j][u] = 0.f;

#pragma unroll 4
            for (int ks = 0; ks < 16; ++ks) {
                const int kw = ks * 8 + t4;
                uint32_t ah[4], al[4];
                ah[0] = Qh32[ar0 + kw];     ah[1] = Qh32[ar1 + kw];
                ah[2] = Qh32[ar0 + kw + 4]; ah[3] = Qh32[ar1 + kw + 4];
                al[0] = Ql32[ar0 + kw];     al[1] = Ql32[ar1 + kw];
                al[2] = Ql32[ar0 + kw + 4]; al[3] = Ql32[ar1 + kw + 4];
#pragma unroll
                for (int jp = 0; jp < 2; ++jp) {
                    const int br0 = (32 * wc + 16 * jp + g) * QKW;
                    const int br1 = (32 * wc + 16 * jp + 8 + g) * QKW;
                    uint32_t bh0 = Kh32[br0 + kw], bh1 = Kh32[br0 + kw + 4];
                    uint32_t bh2 = Kh32[br1 + kw], bh3 = Kh32[br1 + kw + 4];
                    uint32_t bl0 = Kl32[br0 + kw], bl1 = Kl32[br0 + kw + 4];
                    uint32_t bl2 = Kl32[br1 + kw], bl3 = Kl32[br1 + kw + 4];
                    mma_bf16(s[2 * jp],     ah, bh0, bh1);
                    mma_bf16(s[2 * jp],     al, bh0, bh1);
                    mma_bf16(s[2 * jp],     ah, bl0, bl1);
                    mma_bf16(s[2 * jp + 1], ah, bh2, bh3);
                    mma_bf16(s[2 * jp + 1], al, bh2, bh3);
                    mma_bf16(s[2 * jp + 1], ah, bl2, bl3);
                }
            }

            // ---- epilogue: p = exp(min(s/16,10)) masked; den; P fp16 hi/lo
            {
#pragma unroll
                for (int j = 0; j < 4; ++j) {
                    uint32_t bb = mbits >> (4 * j);
                    float p0 = (bb & 1u) ? __expf(fminf(s[j][0] * 0.0625f, 10.f)) : 0.f;
                    float p1 = (bb & 2u) ? __expf(fminf(s[j][1] * 0.0625f, 10.f)) : 0.f;
                    float p2 = (bb & 4u) ? __expf(fminf(s[j][2] * 0.0625f, 10.f)) : 0.f;
                    float p3 = (bb & 8u) ? __expf(fminf(s[j][3] * 0.0625f, 10.f)) : 0.f;
                    denA += p0 + p1;
                    denB += p2 + p3;
                    __half2 h1, l1, h2, l2;
                    h1.x = __float2half_rn(p0); h1.y = __float2half_rn(p1);
                    l1.x = __float2half_rn(p0 - __half2float(h1.x));
                    l1.y = __float2half_rn(p1 - __half2float(h1.y));
                    h2.x = __float2half_rn(p2); h2.y = __float2half_rn(p3);
                    l2.x = __float2half_rn(p2 - __half2float(h2.x));
                    l2.y = __float2half_rn(p3 - __half2float(h2.y));
                    int col = 32 * wc + 2 * t4 + 8 * j;
                    uint32_t w1 = (uint32_t)((16 * wr + g) * VPW + (col >> 1));
                    uint32_t w2 = (uint32_t)((16 * wr + g + 8) * VPW + (col >> 1));
                    ((uint32_t*)(smem + PH_OFF))[w1] = *(uint32_t*)&h1;
                    ((uint32_t*)(smem + PL_OFF))[w1] = *(uint32_t*)&l1;
                    ((uint32_t*)(smem + PH_OFF))[w2] = *(uint32_t*)&h2;
                    ((uint32_t*)(smem + PL_OFF))[w2] = *(uint32_t*)&l2;
                }
            }
            __syncthreads();  // P visible; all warps done with K (phase A)

            // prefetch next tile's K — overlaps all of phase B
            if (kt + 1 < 32) { stage_K(k0 + 64); CP_COMMIT(); }

            // ---- Phase B: O += P V^T (fp16 2-term: Ph*Vh + Pl*Vh)
#pragma unroll
            for (int ks = 0; ks < 4; ++ks) {
                const int kw = ks * 8 + t4;
                uint32_t ah[4], al[4];
                ah[0] = Ph32[pr0 + kw];     ah[1] = Ph32[pr1 + kw];
                ah[2] = Ph32[pr0 + kw + 4]; ah[3] = Ph32[pr1 + kw + 4];
                al[0] = Pl32[pr0 + kw];     al[1] = Pl32[pr1 + kw];
                al[2] = Pl32[pr0 + kw + 4]; al[3] = Pl32[pr1 + kw + 4];
#pragma unroll
                for (int jp = 0; jp < 8; ++jp) {
                    const int vr0 = (128 * wc + 16 * jp + g) * VPW;
                    const int vr1 = (128 * wc + 16 * jp + 8 + g) * VPW;
                    uint32_t bh0 = Vt32[vr0 + kw], bh1 = Vt32[vr0 + kw + 4];
                    uint32_t bh2 = Vt32[vr1 + kw], bh3 = Vt32[vr1 + kw + 4];
                    mma_f16(o[2 * jp],     ah, bh0, bh1);
                    mma_f16(o[2 * jp],     al, bh0, bh1);
                    mma_f16(o[2 * jp + 1], ah, bh2, bh3);
                    mma_f16(o[2 * jp + 1], al, bh2, bh3);
                }
            }
            __syncthreads();  // all warps done with V (phase B) and P

            // prefetch next tile's V — overlaps next tile's mask loads
            if (kt + 1 < 32) { stage_V(k0 + 64); CP_COMMIT(); }
        }

        denA += __shfl_xor_sync(0xffffffffu, denA, 1);
        denA += __shfl_xor_sync(0xffffffffu, denA, 2);
        denB += __shfl_xor_sync(0xffffffffu, denB, 1);
        denB += __shfl_xor_sync(0xffffffffu, denB, 2);
        __syncthreads();
        if (t4 == 0) {
            den_s[wc * 64 + 16 * wr + g] = denA;
            den_s[wc * 64 + 16 * wr + g + 8] = denB;
        }
        __syncthreads();

        {
            const int q1row = 16 * wr + g;
            const float inv1 = 1.0f / (den_s[q1row] + den_s[64 + q1row]);
            const float inv2 = 1.0f / (den_s[q1row + 8] + den_s[64 + q1row + 8]);
            float* o1 = out + ((size_t)b * NS + q0 + q1row) * NF;
            float* o2 = out + ((size_t)b * NS + q0 + q1row + 8) * NF;
#pragma unroll
            for (int j2 = 0; j2 < 16; ++j2) {
                int f = 128 * wc + 8 * j2 + 2 * t4;
                float2 v1, v2;
                v1.x = o[j2][0] * inv1; v1.y = o[j2][1] * inv1;
                v2.x = o[j2][2] * inv2; v2.y = o[j2][3] * inv2;
                *(float2*)(o1 + f) = v1;
                *(float2*)(o2 + f) = v2;
            }
        }
    }
}

// ---------------------------------------------------------------------------
extern "C" void kernel_launch(void* const* d_in, const int* in_sizes, int n_in,
                              void* d_out, int out_size)
{
    const float* seq  = (const float*)d_in[0];
    const float* pos  = (const float*)d_in[1];
    const float* tim  = (const float*)d_in[2];
    const float* Wq   = (const float*)d_in[3];
    const float* Wk   = (const float*)d_in[4];
    const float* cm   = (const float*)d_in[5];
    const int*   caus = (const int*)d_in[6];
    float* out = (float*)d_out;

    cudaFuncSetAttribute(proj_mma, cudaFuncAttributeMaxDynamicSharedMemorySize, PSMEM);
    cudaFuncSetAttribute(attn_mma, cudaFuncAttributeMaxDynamicSharedMemorySize, ASMEM);

    dim3 gp(NB * NS / 128, NDK / 128, 2);   // (128, 2, 2) = 512 CTAs
    proj_mma<<<gp, 256, PSMEM>>>(seq, pos, tim, Wq, Wk);

    dim3 gv(NS / 32, NF / 32, NB);
    vsplit_kernel<<<gv, dim3(32, 8)>>>(seq);

    dim3 ga(16, NB);   // 128 CTAs, 33 key-tiles each (causal), 1 wave
    attn_mma<<<ga, 256, ASMEM>>>(cm, caus, out);
}

// round 14
// speedup vs baseline: 1.4220x; 1.2160x over previous
#include <cuda_runtime.h>
#include <cuda_bf16.h>
#include <cuda_fp16.h>
#include <cstdint>

#define NB 8
#define NS 2048
#define NF 256
#define NE 64
#define NDK 256
#define NIN 384

__device__ __forceinline__ void mma_bf16(float d[4], const uint32_t a[4],
                                         uint32_t b0, uint32_t b1) {
    asm volatile(
        "mma.sync.aligned.m16n8k16.row.col.f32.bf16.bf16.f32 "
        "{%0,%1,%2,%3}, {%4,%5,%6,%7}, {%8,%9}, {%0,%1,%2,%3};"
        : "+f"(d[0]), "+f"(d[1]), "+f"(d[2]), "+f"(d[3])
        : "r"(a[0]), "r"(a[1]), "r"(a[2]), "r"(a[3]), "r"(b0), "r"(b1));
}
__device__ __forceinline__ void mma_f16(float d[4], const uint32_t a[4],
                                        uint32_t b0, uint32_t b1) {
    asm volatile(
        "mma.sync.aligned.m16n8k16.row.col.f32.f16.f16.f32 "
        "{%0,%1,%2,%3}, {%4,%5,%6,%7}, {%8,%9}, {%0,%1,%2,%3};"
        : "+f"(d[0]), "+f"(d[1]), "+f"(d[2]), "+f"(d[3])
        : "r"(a[0]), "r"(a[1]), "r"(a[2]), "r"(a[3]), "r"(b0), "r"(b1));
}

__device__ __forceinline__ uint32_t pack_hi2(float a, float b, uint32_t& lo) {
    __nv_bfloat162 h, l;
    h.x = __float2bfloat16_rn(a); h.y = __float2bfloat16_rn(b);
    l.x = __float2bfloat16_rn(a - __bfloat162float(h.x));
    l.y = __float2bfloat16_rn(b - __bfloat162float(h.y));
    lo = *(uint32_t*)&l;
    return *(uint32_t*)&h;
}

__device__ __forceinline__ uint32_t smem_u32(const void* p) {
    uint32_t a;
    asm("{ .reg .u64 t; cvta.to.shared.u64 t, %1; cvt.u32.u64 %0, t; }"
        : "=r"(a) : "l"(p));
    return a;
}

#define CP16(dst, src) \
    asm volatile("cp.async.cg.shared.global [%0], [%1], 16;" \
                 :: "r"(dst), "l"(src))
#define CP_COMMIT()   asm volatile("cp.async.commit_group;" ::: "memory")
#define CP_WAIT_ALL() asm volatile("cp.async.wait_all;" ::: "memory")

// ---------------------------------------------------------------------------
// Global scratch: Q/K single fp16, V^T single fp16
// ---------------------------------------------------------------------------
__device__ __half g_q[(size_t)NB * NS * NDK];
__device__ __half g_k[(size_t)NB * NS * NDK];
__device__ __half g_vt[(size_t)NB * NF * NS];   // [b][f][s]

// ---------------------------------------------------------------------------
// Kernel 1: Q/K projection via bf16-split HMMA (internals unchanged),
// output = single fp16.  K chunk 64, smem 72KB -> 2 CTAs/SM.
// ---------------------------------------------------------------------------
#define XW      36
#define XH_OFF  0
#define XL_OFF  18432
#define WH_OFF  36864
#define WL_OFF  55296
#define PSMEM   73728

__global__ __launch_bounds__(256, 2) void proj_mma(
    const float* __restrict__ seq, const float* __restrict__ pos,
    const float* __restrict__ tim, const float* __restrict__ Wq,
    const float* __restrict__ Wk)
{
    extern __shared__ char smem[];
    const int tid = threadIdx.x, wid = tid >> 5, lane = tid & 31;
    const int wr = wid & 3, wc = wid >> 2;
    const int g = lane >> 2, t4 = lane & 3;
    const int m0 = blockIdx.x * 128, n0 = blockIdx.y * 128;
    const float* W = blockIdx.z ? Wk : Wq;
    __half* dst = blockIdx.z ? g_k : g_q;

    uint32_t* Xh = (uint32_t*)(smem + XH_OFF);
    uint32_t* Xl = (uint32_t*)(smem + XL_OFF);
    uint32_t* Wh = (uint32_t*)(smem + WH_OFF);
    uint32_t* Wl = (uint32_t*)(smem + WL_OFF);

    float acc[2][8][4];
#pragma unroll
    for (int mi = 0; mi < 2; ++mi)
#pragma unroll
        for (int jn = 0; jn < 8; ++jn)
#pragma unroll
            for (int u = 0; u < 4; ++u) acc[mi][jn][u] = 0.f;

    for (int ch = 0; ch < 6; ++ch) {
        const float* xsrc; int xw, xcol;
        if (ch < 4)      { xsrc = seq; xw = NF; xcol = ch * 64; }
        else if (ch < 5) { xsrc = pos; xw = NE; xcol = 0; }
        else             { xsrc = tim; xw = NE; xcol = 0; }
        const int wcol = ch * 64;

        __syncthreads();
        for (int i = tid; i < 2048; i += 256) {
            int row = i >> 4, cc = (i & 15) * 4;
            float4 xv = *(const float4*)(xsrc + (size_t)(m0 + row) * xw + xcol + cc);
            uint32_t l0, l1;
            uint32_t h0 = pack_hi2(xv.x, xv.y, l0);
            uint32_t h1 = pack_hi2(xv.z, xv.w, l1);
            int w = row * XW + (cc >> 1);
            *(uint2*)(Xh + w) = make_uint2(h0, h1);
            *(uint2*)(Xl + w) = make_uint2(l0, l1);

            float4 wv = *(const float4*)(W + (size_t)(n0 + row) * NIN + wcol + cc);
            uint32_t wl0, wl1;
            uint32_t wh0 = pack_hi2(wv.x, wv.y, wl0);
            uint32_t wh1 = pack_hi2(wv.z, wv.w, wl1);
            *(uint2*)(Wh + w) = make_uint2(wh0, wh1);
            *(uint2*)(Wl + w) = make_uint2(wl0, wl1);
        }
        __syncthreads();

#pragma unroll
        for (int ks = 0; ks < 4; ++ks) {
            const int kw = ks * 8 + t4;
            uint32_t ah[2][4], al[2][4];
#pragma unroll
            for (int mi = 0; mi < 2; ++mi) {
                int r0 = (32 * wr + 16 * mi + g) * XW, r1 = r0 + 8 * XW;
                ah[mi][0] = Xh[r0 + kw];     ah[mi][1] = Xh[r1 + kw];
                ah[mi][2] = Xh[r0 + kw + 4]; ah[mi][3] = Xh[r1 + kw + 4];
                al[mi][0] = Xl[r0 + kw];     al[mi][1] = Xl[r1 + kw];
                al[mi][2] = Xl[r0 + kw + 4]; al[mi][3] = Xl[r1 + kw + 4];
            }
#pragma unroll
            for (int jn = 0; jn < 8; ++jn) {
                int br = (64 * wc + 8 * jn + g) * XW;
                uint32_t bh0 = Wh[br + kw], bh1 = Wh[br + kw + 4];
                uint32_t bl0 = Wl[br + kw], bl1 = Wl[br + kw + 4];
#pragma unroll
                for (int mi = 0; mi < 2; ++mi) {
                    mma_bf16(acc[mi][jn], ah[mi], bh0, bh1);
                    mma_bf16(acc[mi][jn], al[mi], bh0, bh1);
                    mma_bf16(acc[mi][jn], ah[mi], bl0, bl1);
                }
            }
        }
    }

    // output: single fp16
#pragma unroll
    for (int mi = 0; mi < 2; ++mi) {
        int m1 = m0 + 32 * wr + 16 * mi + g;
        int m2 = m1 + 8;
#pragma unroll
        for (int jn = 0; jn < 8; ++jn) {
            int n = n0 + 64 * wc + 8 * jn + 2 * t4;
            __half2 v1, v2;
            v1.x = __float2half_rn(acc[mi][jn][0]);
            v1.y = __float2half_rn(acc[mi][jn][1]);
            v2.x = __float2half_rn(acc[mi][jn][2]);
            v2.y = __float2half_rn(acc[mi][jn][3]);
            *(__half2*)(dst + (size_t)m1 * NDK + n) = v1;
            *(__half2*)(dst + (size_t)m2 * NDK + n) = v2;
        }
    }
}

// ---------------------------------------------------------------------------
// Kernel 2: V = seq transpose -> fp16: g_vt[b][f][s]
// ---------------------------------------------------------------------------
__global__ __launch_bounds__(256) void vsplit_kernel(const float* __restrict__ seq)
{
    __shared__ float t[32][33];
    const int b = blockIdx.z, s0 = blockIdx.x * 32, f0 = blockIdx.y * 32;
    const int tx = threadIdx.x, ty = threadIdx.y;
#pragma unroll
    for (int r = 0; r < 4; ++r) {
        int sl = ty + r * 8;
        t[sl][tx] = seq[((size_t)b * NS + s0 + sl) * NF + f0 + tx];
    }
    __syncthreads();
#pragma unroll
    for (int r = 0; r < 4; ++r) {
        int fl = ty + r * 8;
        g_vt[((size_t)b * NF + f0 + fl) * NS + s0 + tx] = __float2half_rn(t[tx][fl]);
    }
}

// ---------------------------------------------------------------------------
// Kernel 3: fused attention.
// Phase A: QK^T single fp16 term (32 MMAs/warp/tile).
// Phase B: PV fp16 2-term (Ph*V + Pl*V, 64 MMAs/warp/tile).
// cp.async pipeline as in R12.  smem 123KB.
// ---------------------------------------------------------------------------
#define QKW      132   /* uint32 words per Q/K row: (256+8 pad) fp16 */
#define VPW      36    /* uint32 words per VT/P row: (64+8 pad) fp16 */
#define Q_OFF    0
#define K_OFF    33792
#define VT_OFF   67584
#define PH_OFF   104448
#define PL_OFF   113664
#define DEN_OFF  122880
#define ASMEM    123392

__global__ __launch_bounds__(256, 1) void attn_mma(
    const float* __restrict__ cmask,
    const int*   __restrict__ causality,
    float* __restrict__ out)
{
    extern __shared__ char smem[];
    const uint32_t sb = smem_u32(smem);
    const int tid = threadIdx.x;
    const int wid = tid >> 5, lane = tid & 31;
    const int wr = wid & 3, wc = wid >> 2;   // q-band, f-half
    const int g = lane >> 2, t4 = lane & 3;  // fragment row, quad index
    const int b = blockIdx.y;
    const int causal = causality[0];

    const uint32_t* Q32  = (const uint32_t*)(smem + Q_OFF);
    const uint32_t* K32  = (const uint32_t*)(smem + K_OFF);
    const uint32_t* Vt32 = (const uint32_t*)(smem + VT_OFF);
    const uint32_t* Ph32 = (const uint32_t*)(smem + PH_OFF);
    const uint32_t* Pl32 = (const uint32_t*)(smem + PL_OFF);
    float* den_s = (float*)(smem + DEN_OFF);

    const int ar0 = (16 * wr + g) * QKW;
    const int ar1 = (16 * wr + g + 8) * QKW;
    const int pr0 = (16 * wr + g) * VPW;
    const int pr1 = (16 * wr + g + 8) * VPW;

    auto stage_K = [&](int k0) {
        const __half* k = g_k + ((size_t)b * NS + k0) * NDK;
        for (int i = tid; i < 2048; i += 256) {
            int row = i >> 5, c8 = (i & 31) << 3;
            uint32_t off = (uint32_t)(row * (QKW * 2) + c8) * 2;
            CP16(sb + K_OFF + off, k + (size_t)row * NDK + c8);
        }
    };
    auto stage_V = [&](int k0) {
        const __half* vh = g_vt + (size_t)b * NF * NS + k0;
        for (int i = tid; i < 2048; i += 256) {
            int f = i >> 3, k8 = (i & 7) << 3;
            uint32_t off = (uint32_t)(f * (VPW * 2) + k8) * 2;
            CP16(sb + VT_OFF + off, vh + (size_t)f * NS + k8);
        }
    };

    for (int half = 0; half < 2; ++half) {
        const int qt = half ? (31 - (int)blockIdx.x) : (int)blockIdx.x;
        const int q0 = qt * 64;

        __syncthreads();  // previous half fully done before Q restage

        {
            const __half* q = g_q + ((size_t)b * NS + q0) * NDK;
            for (int i = tid; i < 2048; i += 256) {
                int row = i >> 5, c8 = (i & 31) << 3;
                uint32_t off = (uint32_t)(row * (QKW * 2) + c8) * 2;
                *(uint4*)(smem + Q_OFF + off) = *(const uint4*)(q + (size_t)row * NDK + c8);
            }
        }

        float o[16][4];
#pragma unroll
        for (int j = 0; j < 16; ++j)
#pragma unroll
            for (int u = 0; u < 4; ++u) o[j][u] = 0.f;
        float denA = 0.f, denB = 0.f;

        const int kt0 = causal ? qt : 0;

        stage_K(kt0 * 64);
        stage_V(kt0 * 64);
        CP_COMMIT();

        for (int kt = kt0; kt < 32; ++kt) {
            const int k0 = kt * 64;

            // mask bits (overlaps in-flight cp.async)
            uint32_t mbits = 0;
            {
                const int q1 = q0 + 16 * wr + g;
                const int q2 = q1 + 8;
                const int kbase = k0 + 32 * wc + 2 * t4;
                const float* m1p = cmask + ((size_t)b * NS + q1) * NS;
                const float* m2p = cmask + ((size_t)b * NS + q2) * NS;
#pragma unroll
                for (int j = 0; j < 4; ++j) {
                    int kg = kbase + 8 * j;
                    float2 m1 = *(const float2*)(m1p + kg);
                    float2 m2 = *(const float2*)(m2p + kg);
                    uint32_t bits = 0;
                    if (m1.x > 0.f && (!causal || kg     >= q1)) bits |= 1u;
                    if (m1.y > 0.f && (!causal || kg + 1 >= q1)) bits |= 2u;
                    if (m2.x > 0.f && (!causal || kg     >= q2)) bits |= 4u;
                    if (m2.y > 0.f && (!causal || kg + 1 >= q2)) bits |= 8u;
                    mbits |= bits << (4 * j);
                }
            }

            CP_WAIT_ALL();
            __syncthreads();  // K/V (and Q on first iter) visible

            // ---- Phase A: S = Q K^T (single fp16 term)
            float s[4][4];
#pragma unroll
            for (int j = 0; j < 4; ++j)
#pragma unroll
                for (int u = 0; u < 4; ++u) s[j][u] = 0.f;

#pragma unroll 4
            for (int ks = 0; ks < 16; ++ks) {
                const int kw = ks * 8 + t4;
                uint32_t a[4];
                a[0] = Q32[ar0 + kw];     a[1] = Q32[ar1 + kw];
                a[2] = Q32[ar0 + kw + 4]; a[3] = Q32[ar1 + kw + 4];
#pragma unroll
                for (int jp = 0; jp < 2; ++jp) {
                    const int br0 = (32 * wc + 16 * jp + g) * QKW;
                    const int br1 = (32 * wc + 16 * jp + 8 + g) * QKW;
                    uint32_t b0 = K32[br0 + kw], b1 = K32[br0 + kw + 4];
                    uint32_t b2 = K32[br1 + kw], b3 = K32[br1 + kw + 4];
                    mma_f16(s[2 * jp],     a, b0, b1);
                    mma_f16(s[2 * jp + 1], a, b2, b3);
                }
            }

            // ---- epilogue: p = exp(min(s/16,10)) masked; den; P fp16 hi/lo
            {
#pragma unroll
                for (int j = 0; j < 4; ++j) {
                    uint32_t bb = mbits >> (4 * j);
                    float p0 = (bb & 1u) ? __expf(fminf(s[j][0] * 0.0625f, 10.f)) : 0.f;
                    float p1 = (bb & 2u) ? __expf(fminf(s[j][1] * 0.0625f, 10.f)) : 0.f;
                    float p2 = (bb & 4u) ? __expf(fminf(s[j][2] * 0.0625f, 10.f)) : 0.f;
                    float p3 = (bb & 8u) ? __expf(fminf(s[j][3] * 0.0625f, 10.f)) : 0.f;
                    denA += p0 + p1;
                    denB += p2 + p3;
                    __half2 h1, l1, h2, l2;
                    h1.x = __float2half_rn(p0); h1.y = __float2half_rn(p1);
                    l1.x = __float2half_rn(p0 - __half2float(h1.x));
                    l1.y = __float2half_rn(p1 - __half2float(h1.y));
                    h2.x = __float2half_rn(p2); h2.y = __float2half_rn(p3);
                    l2.x = __float2half_rn(p2 - __half2float(h2.x));
                    l2.y = __float2half_rn(p3 - __half2float(h2.y));
                    int col = 32 * wc + 2 * t4 + 8 * j;
                    uint32_t w1 = (uint32_t)((16 * wr + g) * VPW + (col >> 1));
                    uint32_t w2 = (uint32_t)((16 * wr + g + 8) * VPW + (col >> 1));
                    ((uint32_t*)(smem + PH_OFF))[w1] = *(uint32_t*)&h1;
                    ((uint32_t*)(smem + PL_OFF))[w1] = *(uint32_t*)&l1;
                    ((uint32_t*)(smem + PH_OFF))[w2] = *(uint32_t*)&h2;
                    ((uint32_t*)(smem + PL_OFF))[w2] = *(uint32_t*)&l2;
                }
            }
            __syncthreads();  // P visible; all warps done with K (phase A)

            // prefetch next tile's K — overlaps all of phase B
            if (kt + 1 < 32) { stage_K(k0 + 64); CP_COMMIT(); }

            // ---- Phase B: O += P V^T (fp16 2-term: Ph*V + Pl*V)
#pragma unroll
            for (int ks = 0; ks < 4; ++ks) {
                const int kw = ks * 8 + t4;
                uint32_t ah[4], al[4];
                ah[0] = Ph32[pr0 + kw];     ah[1] = Ph32[pr1 + kw];
                ah[2] = Ph32[pr0 + kw + 4]; ah[3] = Ph32[pr1 + kw + 4];
                al[0] = Pl32[pr0 + kw];     al[1] = Pl32[pr1 + kw];
                al[2] = Pl32[pr0 + kw + 4]; al[3] = Pl32[pr1 + kw + 4];
#pragma unroll
                for (int jp = 0; jp < 8; ++jp) {
                    const int vr0 = (128 * wc + 16 * jp + g) * VPW;
                    const int vr1 = (128 * wc + 16 * jp + 8 + g) * VPW;
                    uint32_t b0 = Vt32[vr0 + kw], b1 = Vt32[vr0 + kw + 4];
                    uint32_t b2 = Vt32[vr1 + kw], b3 = Vt32[vr1 + kw + 4];
                    mma_f16(o[2 * jp],     ah, b0, b1);
                    mma_f16(o[2 * jp],     al, b0, b1);
                    mma_f16(o[2 * jp + 1], ah, b2, b3);
                    mma_f16(o[2 * jp + 1], al, b2, b3);
                }
            }
            __syncthreads();  // all warps done with V (phase B) and P

            // prefetch next tile's V — overlaps next tile's mask loads
            if (kt + 1 < 32) { stage_V(k0 + 64); CP_COMMIT(); }
        }

        denA += __shfl_xor_sync(0xffffffffu, denA, 1);
        denA += __shfl_xor_sync(0xffffffffu, denA, 2);
        denB += __shfl_xor_sync(0xffffffffu, denB, 1);
        denB += __shfl_xor_sync(0xffffffffu, denB, 2);
        __syncthreads();
        if (t4 == 0) {
            den_s[wc * 64 + 16 * wr + g] = denA;
            den_s[wc * 64 + 16 * wr + g + 8] = denB;
        }
        __syncthreads();

        {
            const int q1row = 16 * wr + g;
            const float inv1 = 1.0f / (den_s[q1row] + den_s[64 + q1row]);
            const float inv2 = 1.0f / (den_s[q1row + 8] + den_s[64 + q1row + 8]);
            float* o1 = out + ((size_t)b * NS + q0 + q1row) * NF;
            float* o2 = out + ((size_t)b * NS + q0 + q1row + 8) * NF;
#pragma unroll
            for (int j2 = 0; j2 < 16; ++j2) {
                int f = 128 * wc + 8 * j2 + 2 * t4;
                float2 v1, v2;
                v1.x = o[j2][0] * inv1; v1.y = o[j2][1] * inv1;
                v2.x = o[j2][2] * inv2; v2.y = o[j2][3] * inv2;
                *(float2*)(o1 + f) = v1;
                *(float2*)(o2 + f) = v2;
            }
        }
    }
}

// ---------------------------------------------------------------------------
extern "C" void kernel_launch(void* const* d_in, const int* in_sizes, int n_in,
                              void* d_out, int out_size)
{
    const float* seq  = (const float*)d_in[0];
    const float* pos  = (const float*)d_in[1];
    const float* tim  = (const float*)d_in[2];
    const float* Wq   = (const float*)d_in[3];
    const float* Wk   = (const float*)d_in[4];
    const float* cm   = (const float*)d_in[5];
    const int*   caus = (const int*)d_in[6];
    float* out = (float*)d_out;

    cudaFuncSetAttribute(proj_mma, cudaFuncAttributeMaxDynamicSharedMemorySize, PSMEM);
    cudaFuncSetAttribute(attn_mma, cudaFuncAttributeMaxDynamicSharedMemorySize, ASMEM);

    dim3 gp(NB * NS / 128, NDK / 128, 2);   // (128, 2, 2) = 512 CTAs
    proj_mma<<<gp, 256, PSMEM>>>(seq, pos, tim, Wq, Wk);

    dim3 gv(NS / 32, NF / 32, NB);
    vsplit_kernel<<<gv, dim3(32, 8)>>>(seq);

    dim3 ga(16, NB);   // 128 CTAs, 33 key-tiles each (causal), 1 wave
    attn_mma<<<ga, 256, ASMEM>>>(cm, caus, out);
}

// round 15
// speedup vs baseline: 1.6522x; 1.1618x over previous
#include <cuda_runtime.h>
#include <cuda_bf16.h>
#include <cuda_fp16.h>
#include <cstdint>

#define NB 8
#define NS 2048
#define NF 256
#define NE 64
#define NDK 256
#define NIN 384

__device__ __forceinline__ void mma_f16(float d[4], const uint32_t a[4],
                                        uint32_t b0, uint32_t b1) {
    asm volatile(
        "mma.sync.aligned.m16n8k16.row.col.f32.f16.f16.f32 "
        "{%0,%1,%2,%3}, {%4,%5,%6,%7}, {%8,%9}, {%0,%1,%2,%3};"
        : "+f"(d[0]), "+f"(d[1]), "+f"(d[2]), "+f"(d[3])
        : "r"(a[0]), "r"(a[1]), "r"(a[2]), "r"(a[3]), "r"(b0), "r"(b1));
}

__device__ __forceinline__ uint32_t pack2_f16(float a, float b) {
    __half2 h;
    h.x = __float2half_rn(a); h.y = __float2half_rn(b);
    return *(uint32_t*)&h;
}
__device__ __forceinline__ uint32_t pack_hi2_f16(float a, float b, uint32_t& lo) {
    __half2 h, l;
    h.x = __float2half_rn(a); h.y = __float2half_rn(b);
    l.x = __float2half_rn(a - __half2float(h.x));
    l.y = __float2half_rn(b - __half2float(h.y));
    lo = *(uint32_t*)&l;
    return *(uint32_t*)&h;
}

__device__ __forceinline__ uint32_t smem_u32(const void* p) {
    uint32_t a;
    asm("{ .reg .u64 t; cvta.to.shared.u64 t, %1; cvt.u32.u64 %0, t; }"
        : "=r"(a) : "l"(p));
    return a;
}

#define CP16(dst, src) \
    asm volatile("cp.async.cg.shared.global [%0], [%1], 16;" \
                 :: "r"(dst), "l"(src))
#define CP_COMMIT()   asm volatile("cp.async.commit_group;" ::: "memory")
#define CP_WAIT_ALL() asm volatile("cp.async.wait_all;" ::: "memory")

// ---------------------------------------------------------------------------
// Global scratch: Q/K single fp16, V^T single fp16
// ---------------------------------------------------------------------------
__device__ __half g_q[(size_t)NB * NS * NDK];
__device__ __half g_k[(size_t)NB * NS * NDK];
__device__ __half g_vt[(size_t)NB * NF * NS];   // [b][f][s]

// ---------------------------------------------------------------------------
// Kernel 1: Q/K projection via fp16 2-term HMMA (Xh+Xl split, W single),
// fp32 accum.  K chunk 64, smem 54KB -> 2 CTAs/SM.
// ---------------------------------------------------------------------------
#define XW      36
#define XH_OFF  0
#define XL_OFF  18432
#define WH_OFF  36864
#define PSMEM   55296

__global__ __launch_bounds__(256, 2) void proj_mma(
    const float* __restrict__ seq, const float* __restrict__ pos,
    const float* __restrict__ tim, const float* __restrict__ Wq,
    const float* __restrict__ Wk)
{
    extern __shared__ char smem[];
    const int tid = threadIdx.x, wid = tid >> 5, lane = tid & 31;
    const int wr = wid & 3, wc = wid >> 2;
    const int g = lane >> 2, t4 = lane & 3;
    const int m0 = blockIdx.x * 128, n0 = blockIdx.y * 128;
    const float* W = blockIdx.z ? Wk : Wq;
    __half* dst = blockIdx.z ? g_k : g_q;

    uint32_t* Xh = (uint32_t*)(smem + XH_OFF);
    uint32_t* Xl = (uint32_t*)(smem + XL_OFF);
    uint32_t* Wh = (uint32_t*)(smem + WH_OFF);

    float acc[2][8][4];
#pragma unroll
    for (int mi = 0; mi < 2; ++mi)
#pragma unroll
        for (int jn = 0; jn < 8; ++jn)
#pragma unroll
            for (int u = 0; u < 4; ++u) acc[mi][jn][u] = 0.f;

    for (int ch = 0; ch < 6; ++ch) {
        const float* xsrc; int xw, xcol;
        if (ch < 4)      { xsrc = seq; xw = NF; xcol = ch * 64; }
        else if (ch < 5) { xsrc = pos; xw = NE; xcol = 0; }
        else             { xsrc = tim; xw = NE; xcol = 0; }
        const int wcol = ch * 64;

        __syncthreads();
        for (int i = tid; i < 2048; i += 256) {
            int row = i >> 4, cc = (i & 15) * 4;
            float4 xv = *(const float4*)(xsrc + (size_t)(m0 + row) * xw + xcol + cc);
            uint32_t l0, l1;
            uint32_t h0 = pack_hi2_f16(xv.x, xv.y, l0);
            uint32_t h1 = pack_hi2_f16(xv.z, xv.w, l1);
            int w = row * XW + (cc >> 1);
            *(uint2*)(Xh + w) = make_uint2(h0, h1);
            *(uint2*)(Xl + w) = make_uint2(l0, l1);

            float4 wv = *(const float4*)(W + (size_t)(n0 + row) * NIN + wcol + cc);
            *(uint2*)(Wh + w) = make_uint2(pack2_f16(wv.x, wv.y),
                                           pack2_f16(wv.z, wv.w));
        }
        __syncthreads();

#pragma unroll
        for (int ks = 0; ks < 4; ++ks) {
            const int kw = ks * 8 + t4;
            uint32_t ah[2][4], al[2][4];
#pragma unroll
            for (int mi = 0; mi < 2; ++mi) {
                int r0 = (32 * wr + 16 * mi + g) * XW, r1 = r0 + 8 * XW;
                ah[mi][0] = Xh[r0 + kw];     ah[mi][1] = Xh[r1 + kw];
                ah[mi][2] = Xh[r0 + kw + 4]; ah[mi][3] = Xh[r1 + kw + 4];
                al[mi][0] = Xl[r0 + kw];     al[mi][1] = Xl[r1 + kw];
                al[mi][2] = Xl[r0 + kw + 4]; al[mi][3] = Xl[r1 + kw + 4];
            }
#pragma unroll
            for (int jn = 0; jn < 8; ++jn) {
                int br = (64 * wc + 8 * jn + g) * XW;
                uint32_t b0 = Wh[br + kw], b1 = Wh[br + kw + 4];
#pragma unroll
                for (int mi = 0; mi < 2; ++mi) {
                    mma_f16(acc[mi][jn], ah[mi], b0, b1);
                    mma_f16(acc[mi][jn], al[mi], b0, b1);
                }
            }
        }
    }

    // output: single fp16
#pragma unroll
    for (int mi = 0; mi < 2; ++mi) {
        int m1 = m0 + 32 * wr + 16 * mi + g;
        int m2 = m1 + 8;
#pragma unroll
        for (int jn = 0; jn < 8; ++jn) {
            int n = n0 + 64 * wc + 8 * jn + 2 * t4;
            *(uint32_t*)(dst + (size_t)m1 * NDK + n) =
                pack2_f16(acc[mi][jn][0], acc[mi][jn][1]);
            *(uint32_t*)(dst + (size_t)m2 * NDK + n) =
                pack2_f16(acc[mi][jn][2], acc[mi][jn][3]);
        }
    }
}

// ---------------------------------------------------------------------------
// Kernel 2: V = seq transpose -> fp16: g_vt[b][f][s]
// ---------------------------------------------------------------------------
__global__ __launch_bounds__(256) void vsplit_kernel(const float* __restrict__ seq)
{
    __shared__ float t[32][33];
    const int b = blockIdx.z, s0 = blockIdx.x * 32, f0 = blockIdx.y * 32;
    const int tx = threadIdx.x, ty = threadIdx.y;
#pragma unroll
    for (int r = 0; r < 4; ++r) {
        int sl = ty + r * 8;
        t[sl][tx] = seq[((size_t)b * NS + s0 + sl) * NF + f0 + tx];
    }
    __syncthreads();
#pragma unroll
    for (int r = 0; r < 4; ++r) {
        int fl = ty + r * 8;
        g_vt[((size_t)b * NF + f0 + fl) * NS + s0 + tx] = __float2half_rn(t[tx][fl]);
    }
}

// ---------------------------------------------------------------------------
// Kernel 3: fused attention.
// Phase A: QK^T single fp16 term.  Phase B: PV single fp16 term (P fp16).
// cp.async pipeline as before.  smem 112KB.
// ---------------------------------------------------------------------------
#define QKW      132   /* uint32 words per Q/K row: (256+8 pad) fp16 */
#define VPW      36    /* uint32 words per VT/P row: (64+8 pad) fp16 */
#define Q_OFF    0
#define K_OFF    33792
#define VT_OFF   67584
#define PH_OFF   104448
#define DEN_OFF  113664
#define ASMEM    114176

__global__ __launch_bounds__(256, 1) void attn_mma(
    const float* __restrict__ cmask,
    const int*   __restrict__ causality,
    float* __restrict__ out)
{
    extern __shared__ char smem[];
    const uint32_t sb = smem_u32(smem);
    const int tid = threadIdx.x;
    const int wid = tid >> 5, lane = tid & 31;
    const int wr = wid & 3, wc = wid >> 2;   // q-band, f-half
    const int g = lane >> 2, t4 = lane & 3;  // fragment row, quad index
    const int b = blockIdx.y;
    const int causal = causality[0];

    const uint32_t* Q32  = (const uint32_t*)(smem + Q_OFF);
    const uint32_t* K32  = (const uint32_t*)(smem + K_OFF);
    const uint32_t* Vt32 = (const uint32_t*)(smem + VT_OFF);
    const uint32_t* Ph32 = (const uint32_t*)(smem + PH_OFF);
    float* den_s = (float*)(smem + DEN_OFF);

    const int ar0 = (16 * wr + g) * QKW;
    const int ar1 = (16 * wr + g + 8) * QKW;
    const int pr0 = (16 * wr + g) * VPW;
    const int pr1 = (16 * wr + g + 8) * VPW;

    auto stage_K = [&](int k0) {
        const __half* k = g_k + ((size_t)b * NS + k0) * NDK;
        for (int i = tid; i < 2048; i += 256) {
            int row = i >> 5, c8 = (i & 31) << 3;
            uint32_t off = (uint32_t)(row * (QKW * 2) + c8) * 2;
            CP16(sb + K_OFF + off, k + (size_t)row * NDK + c8);
        }
    };
    auto stage_V = [&](int k0) {
        const __half* vh = g_vt + (size_t)b * NF * NS + k0;
        for (int i = tid; i < 2048; i += 256) {
            int f = i >> 3, k8 = (i & 7) << 3;
            uint32_t off = (uint32_t)(f * (VPW * 2) + k8) * 2;
            CP16(sb + VT_OFF + off, vh + (size_t)f * NS + k8);
        }
    };

    for (int half = 0; half < 2; ++half) {
        const int qt = half ? (31 - (int)blockIdx.x) : (int)blockIdx.x;
        const int q0 = qt * 64;

        __syncthreads();  // previous half fully done before Q restage

        {
            const __half* q = g_q + ((size_t)b * NS + q0) * NDK;
            for (int i = tid; i < 2048; i += 256) {
                int row = i >> 5, c8 = (i & 31) << 3;
                uint32_t off = (uint32_t)(row * (QKW * 2) + c8) * 2;
                *(uint4*)(smem + Q_OFF + off) = *(const uint4*)(q + (size_t)row * NDK + c8);
            }
        }

        float o[16][4];
#pragma unroll
        for (int j = 0; j < 16; ++j)
#pragma unroll
            for (int u = 0; u < 4; ++u) o[j][u] = 0.f;
        float denA = 0.f, denB = 0.f;

        const int kt0 = causal ? qt : 0;

        stage_K(kt0 * 64);
        stage_V(kt0 * 64);
        CP_COMMIT();

        for (int kt = kt0; kt < 32; ++kt) {
            const int k0 = kt * 64;

            // mask bits (overlaps in-flight cp.async)
            uint32_t mbits = 0;
            {
                const int q1 = q0 + 16 * wr + g;
                const int q2 = q1 + 8;
                const int kbase = k0 + 32 * wc + 2 * t4;
                const float* m1p = cmask + ((size_t)b * NS + q1) * NS;
                const float* m2p = cmask + ((size_t)b * NS + q2) * NS;
#pragma unroll
                for (int j = 0; j < 4; ++j) {
                    int kg = kbase + 8 * j;
                    float2 m1 = *(const float2*)(m1p + kg);
                    float2 m2 = *(const float2*)(m2p + kg);
                    uint32_t bits = 0;
                    if (m1.x > 0.f && (!causal || kg     >= q1)) bits |= 1u;
                    if (m1.y > 0.f && (!causal || kg + 1 >= q1)) bits |= 2u;
                    if (m2.x > 0.f && (!causal || kg     >= q2)) bits |= 4u;
                    if (m2.y > 0.f && (!causal || kg + 1 >= q2)) bits |= 8u;
                    mbits |= bits << (4 * j);
                }
            }

            CP_WAIT_ALL();
            __syncthreads();  // K/V (and Q on first iter) visible

            // ---- Phase A: S = Q K^T (single fp16 term)
            float s[4][4];
#pragma unroll
            for (int j = 0; j < 4; ++j)
#pragma unroll
                for (int u = 0; u < 4; ++u) s[j][u] = 0.f;

#pragma unroll 4
            for (int ks = 0; ks < 16; ++ks) {
                const int kw = ks * 8 + t4;
                uint32_t a[4];
                a[0] = Q32[ar0 + kw];     a[1] = Q32[ar1 + kw];
                a[2] = Q32[ar0 + kw + 4]; a[3] = Q32[ar1 + kw + 4];
#pragma unroll
                for (int jp = 0; jp < 2; ++jp) {
                    const int br0 = (32 * wc + 16 * jp + g) * QKW;
                    const int br1 = (32 * wc + 16 * jp + 8 + g) * QKW;
                    uint32_t b0 = K32[br0 + kw], b1 = K32[br0 + kw + 4];
                    uint32_t b2 = K32[br1 + kw], b3 = K32[br1 + kw + 4];
                    mma_f16(s[2 * jp],     a, b0, b1);
                    mma_f16(s[2 * jp + 1], a, b2, b3);
                }
            }

            // ---- epilogue: p = exp(min(s/16,10)) masked; den; P fp16 single
            {
#pragma unroll
                for (int j = 0; j < 4; ++j) {
                    uint32_t bb = mbits >> (4 * j);
                    float p0 = (bb & 1u) ? __expf(fminf(s[j][0] * 0.0625f, 10.f)) : 0.f;
                    float p1 = (bb & 2u) ? __expf(fminf(s[j][1] * 0.0625f, 10.f)) : 0.f;
                    float p2 = (bb & 4u) ? __expf(fminf(s[j][2] * 0.0625f, 10.f)) : 0.f;
                    float p3 = (bb & 8u) ? __expf(fminf(s[j][3] * 0.0625f, 10.f)) : 0.f;
                    denA += p0 + p1;
                    denB += p2 + p3;
                    int col = 32 * wc + 2 * t4 + 8 * j;
                    uint32_t w1 = (uint32_t)((16 * wr + g) * VPW + (col >> 1));
                    uint32_t w2 = (uint32_t)((16 * wr + g + 8) * VPW + (col >> 1));
                    ((uint32_t*)(smem + PH_OFF))[w1] = pack2_f16(p0, p1);
                    ((uint32_t*)(smem + PH_OFF))[w2] = pack2_f16(p2, p3);
                }
            }
            __syncthreads();  // P visible; all warps done with K (phase A)

            // prefetch next tile's K — overlaps all of phase B
            if (kt + 1 < 32) { stage_K(k0 + 64); CP_COMMIT(); }

            // ---- Phase B: O += P V^T (single fp16 term)
#pragma unroll
            for (int ks = 0; ks < 4; ++ks) {
                const int kw = ks * 8 + t4;
                uint32_t a[4];
                a[0] = Ph32[pr0 + kw];     a[1] = Ph32[pr1 + kw];
                a[2] = Ph32[pr0 + kw + 4]; a[3] = Ph32[pr1 + kw + 4];
#pragma unroll
                for (int jp = 0; jp < 8; ++jp) {
                    const int vr0 = (128 * wc + 16 * jp + g) * VPW;
                    const int vr1 = (128 * wc + 16 * jp + 8 + g) * VPW;
                    uint32_t b0 = Vt32[vr0 + kw], b1 = Vt32[vr0 + kw + 4];
                    uint32_t b2 = Vt32[vr1 + kw], b3 = Vt32[vr1 + kw + 4];
                    mma_f16(o[2 * jp],     a, b0, b1);
                    mma_f16(o[2 * jp + 1], a, b2, b3);
                }
            }
            __syncthreads();  // all warps done with V (phase B) and P

            // prefetch next tile's V — overlaps next tile's mask loads
            if (kt + 1 < 32) { stage_V(k0 + 64); CP_COMMIT(); }
        }

        denA += __shfl_xor_sync(0xffffffffu, denA, 1);
        denA += __shfl_xor_sync(0xffffffffu, denA, 2);
        denB += __shfl_xor_sync(0xffffffffu, denB, 1);
        denB += __shfl_xor_sync(0xffffffffu, denB, 2);
        __syncthreads();
        if (t4 == 0) {
            den_s[wc * 64 + 16 * wr + g] = denA;
            den_s[wc * 64 + 16 * wr + g + 8] = denB;
        }
        __syncthreads();

        {
            const int q1row = 16 * wr + g;
            const float inv1 = 1.0f / (den_s[q1row] + den_s[64 + q1row]);
            const float inv2 = 1.0f / (den_s[q1row + 8] + den_s[64 + q1row + 8]);
            float* o1 = out + ((size_t)b * NS + q0 + q1row) * NF;
            float* o2 = out + ((size_t)b * NS + q0 + q1row + 8) * NF;
#pragma unroll
            for (int j2 = 0; j2 < 16; ++j2) {
                int f = 128 * wc + 8 * j2 + 2 * t4;
                float2 v1, v2;
                v1.x = o[j2][0] * inv1; v1.y = o[j2][1] * inv1;
                v2.x = o[j2][2] * inv2; v2.y = o[j2][3] * inv2;
                *(float2*)(o1 + f) = v1;
                *(float2*)(o2 + f) = v2;
            }
        }
    }
}

// ---------------------------------------------------------------------------
extern "C" void kernel_launch(void* const* d_in, const int* in_sizes, int n_in,
                              void* d_out, int out_size)
{
    const float* seq  = (const float*)d_in[0];
    const float* pos  = (const float*)d_in[1];
    const float* tim  = (const float*)d_in[2];
    const float* Wq   = (const float*)d_in[3];
    const float* Wk   = (const float*)d_in[4];
    const float* cm   = (const float*)d_in[5];
    const int*   caus = (const int*)d_in[6];
    float* out = (float*)d_out;

    cudaFuncSetAttribute(proj_mma, cudaFuncAttributeMaxDynamicSharedMemorySize, PSMEM);
    cudaFuncSetAttribute(attn_mma, cudaFuncAttributeMaxDynamicSharedMemorySize, ASMEM);

    dim3 gp(NB * NS / 128, NDK / 128, 2);   // (128, 2, 2) = 512 CTAs
    proj_mma<<<gp, 256, PSMEM>>>(seq, pos, tim, Wq, Wk);

    dim3 gv(NS / 32, NF / 32, NB);
    vsplit_kernel<<<gv, dim3(32, 8)>>>(seq);

    dim3 ga(16, NB);   // 128 CTAs, 33 key-tiles each (causal), 1 wave
    attn_mma<<<ga, 256, ASMEM>>>(cm, caus, out);
}

// round 16
// speedup vs baseline: 1.7799x; 1.0773x over previous
#include <cuda_runtime.h>
#include <cuda_bf16.h>
#include <cuda_fp16.h>
#include <cstdint>

#define NB 8
#define NS 2048
#define NF 256
#define NE 64
#define NDK 256
#define NIN 384

__device__ __forceinline__ void mma_f16(float d[4], const uint32_t a[4],
                                        uint32_t b0, uint32_t b1) {
    asm volatile(
        "mma.sync.aligned.m16n8k16.row.col.f32.f16.f16.f32 "
        "{%0,%1,%2,%3}, {%4,%5,%6,%7}, {%8,%9}, {%0,%1,%2,%3};"
        : "+f"(d[0]), "+f"(d[1]), "+f"(d[2]), "+f"(d[3])
        : "r"(a[0]), "r"(a[1]), "r"(a[2]), "r"(a[3]), "r"(b0), "r"(b1));
}

__device__ __forceinline__ float ex2f(float x) {
    float r;
    asm("ex2.approx.ftz.f32 %0, %1;" : "=f"(r) : "f"(x));
    return r;
}

__device__ __forceinline__ uint32_t pack2_f16(float a, float b) {
    __half2 h;
    h.x = __float2half_rn(a); h.y = __float2half_rn(b);
    return *(uint32_t*)&h;
}
__device__ __forceinline__ uint32_t pack_hi2_f16(float a, float b, uint32_t& lo) {
    __half2 h, l;
    h.x = __float2half_rn(a); h.y = __float2half_rn(b);
    l.x = __float2half_rn(a - __half2float(h.x));
    l.y = __float2half_rn(b - __half2float(h.y));
    lo = *(uint32_t*)&l;
    return *(uint32_t*)&h;
}

__device__ __forceinline__ uint32_t smem_u32(const void* p) {
    uint32_t a;
    asm("{ .reg .u64 t; cvta.to.shared.u64 t, %1; cvt.u32.u64 %0, t; }"
        : "=r"(a) : "l"(p));
    return a;
}

#define CP16(dst, src) \
    asm volatile("cp.async.cg.shared.global [%0], [%1], 16;" \
                 :: "r"(dst), "l"(src))
#define CP_COMMIT()   asm volatile("cp.async.commit_group;" ::: "memory")
#define CP_WAIT_ALL() asm volatile("cp.async.wait_all;" ::: "memory")

// exp2 constants: p = 2^(s_raw * 0.0625 * log2e), clamp at 10*log2e
#define EXPC  0.0901684403f
#define EXPMX 14.4269504f

// ---------------------------------------------------------------------------
// Global scratch: Q/K single fp16, V^T single fp16
// ---------------------------------------------------------------------------
__device__ __half g_q[(size_t)NB * NS * NDK];
__device__ __half g_k[(size_t)NB * NS * NDK];
__device__ __half g_vt[(size_t)NB * NF * NS];   // [b][f][s]

// ---------------------------------------------------------------------------
// Kernel 1: Q/K projection, fp16 2-term HMMA (Xh+Xl, W single), fp32 acc.
// ---------------------------------------------------------------------------
#define XW      36
#define XH_OFF  0
#define XL_OFF  18432
#define WH_OFF  36864
#define PSMEM   55296

__global__ __launch_bounds__(256, 2) void proj_mma(
    const float* __restrict__ seq, const float* __restrict__ pos,
    const float* __restrict__ tim, const float* __restrict__ Wq,
    const float* __restrict__ Wk)
{
    extern __shared__ char smem[];
    const int tid = threadIdx.x, wid = tid >> 5, lane = tid & 31;
    const int wr = wid & 3, wc = wid >> 2;
    const int g = lane >> 2, t4 = lane & 3;
    const int m0 = blockIdx.x * 128, n0 = blockIdx.y * 128;
    const float* W = blockIdx.z ? Wk : Wq;
    __half* dst = blockIdx.z ? g_k : g_q;

    uint32_t* Xh = (uint32_t*)(smem + XH_OFF);
    uint32_t* Xl = (uint32_t*)(smem + XL_OFF);
    uint32_t* Wh = (uint32_t*)(smem + WH_OFF);

    float acc[2][8][4];
#pragma unroll
    for (int mi = 0; mi < 2; ++mi)
#pragma unroll
        for (int jn = 0; jn < 8; ++jn)
#pragma unroll
            for (int u = 0; u < 4; ++u) acc[mi][jn][u] = 0.f;

    for (int ch = 0; ch < 6; ++ch) {
        const float* xsrc; int xw, xcol;
        if (ch < 4)      { xsrc = seq; xw = NF; xcol = ch * 64; }
        else if (ch < 5) { xsrc = pos; xw = NE; xcol = 0; }
        else             { xsrc = tim; xw = NE; xcol = 0; }
        const int wcol = ch * 64;

        __syncthreads();
#pragma unroll
        for (int l = 0; l < 8; ++l) {
            int i = tid + l * 256;
            int row = i >> 4, cc = (i & 15) * 4;
            float4 xv = *(const float4*)(xsrc + (size_t)(m0 + row) * xw + xcol + cc);
            uint32_t l0, l1;
            uint32_t h0 = pack_hi2_f16(xv.x, xv.y, l0);
            uint32_t h1 = pack_hi2_f16(xv.z, xv.w, l1);
            int w = row * XW + (cc >> 1);
            *(uint2*)(Xh + w) = make_uint2(h0, h1);
            *(uint2*)(Xl + w) = make_uint2(l0, l1);

            float4 wv = *(const float4*)(W + (size_t)(n0 + row) * NIN + wcol + cc);
            *(uint2*)(Wh + w) = make_uint2(pack2_f16(wv.x, wv.y),
                                           pack2_f16(wv.z, wv.w));
        }
        __syncthreads();

#pragma unroll
        for (int ks = 0; ks < 4; ++ks) {
            const int kw = ks * 8 + t4;
            uint32_t ah[2][4], al[2][4];
#pragma unroll
            for (int mi = 0; mi < 2; ++mi) {
                int r0 = (32 * wr + 16 * mi + g) * XW, r1 = r0 + 8 * XW;
                ah[mi][0] = Xh[r0 + kw];     ah[mi][1] = Xh[r1 + kw];
                ah[mi][2] = Xh[r0 + kw + 4]; ah[mi][3] = Xh[r1 + kw + 4];
                al[mi][0] = Xl[r0 + kw];     al[mi][1] = Xl[r1 + kw];
                al[mi][2] = Xl[r0 + kw + 4]; al[mi][3] = Xl[r1 + kw + 4];
            }
#pragma unroll
            for (int jn = 0; jn < 8; ++jn) {
                int br = (64 * wc + 8 * jn + g) * XW;
                uint32_t b0 = Wh[br + kw], b1 = Wh[br + kw + 4];
#pragma unroll
                for (int mi = 0; mi < 2; ++mi) {
                    mma_f16(acc[mi][jn], ah[mi], b0, b1);
                    mma_f16(acc[mi][jn], al[mi], b0, b1);
                }
            }
        }
    }

#pragma unroll
    for (int mi = 0; mi < 2; ++mi) {
        int m1 = m0 + 32 * wr + 16 * mi + g;
        int m2 = m1 + 8;
#pragma unroll
        for (int jn = 0; jn < 8; ++jn) {
            int n = n0 + 64 * wc + 8 * jn + 2 * t4;
            *(uint32_t*)(dst + (size_t)m1 * NDK + n) =
                pack2_f16(acc[mi][jn][0], acc[mi][jn][1]);
            *(uint32_t*)(dst + (size_t)m2 * NDK + n) =
                pack2_f16(acc[mi][jn][2], acc[mi][jn][3]);
        }
    }
}

// ---------------------------------------------------------------------------
// Kernel 2: V = seq transpose -> fp16: g_vt[b][f][s]
// ---------------------------------------------------------------------------
__global__ __launch_bounds__(256) void vsplit_kernel(const float* __restrict__ seq)
{
    __shared__ float t[32][33];
    const int b = blockIdx.z, s0 = blockIdx.x * 32, f0 = blockIdx.y * 32;
    const int tx = threadIdx.x, ty = threadIdx.y;
#pragma unroll
    for (int r = 0; r < 4; ++r) {
        int sl = ty + r * 8;
        t[sl][tx] = seq[((size_t)b * NS + s0 + sl) * NF + f0 + tx];
    }
    __syncthreads();
#pragma unroll
    for (int r = 0; r < 4; ++r) {
        int fl = ty + r * 8;
        g_vt[((size_t)b * NF + f0 + fl) * NS + s0 + tx] = __float2half_rn(t[tx][fl]);
    }
}

// ---------------------------------------------------------------------------
// Kernel 3: fused attention.  QK^T fp16 1-term, PV fp16 1-term.
// Epilogue: float-mask multiply (p = ex2(t)*m), causal compares only in the
// diagonal tile, exp2 with folded scale.
// ---------------------------------------------------------------------------
#define QKW      132
#define VPW      36
#define Q_OFF    0
#define K_OFF    33792
#define VT_OFF   67584
#define PH_OFF   104448
#define DEN_OFF  113664
#define ASMEM    114176

__global__ __launch_bounds__(256, 1) void attn_mma(
    const float* __restrict__ cmask,
    const int*   __restrict__ causality,
    float* __restrict__ out)
{
    extern __shared__ char smem[];
    const uint32_t sb = smem_u32(smem);
    const int tid = threadIdx.x;
    const int wid = tid >> 5, lane = tid & 31;
    const int wr = wid & 3, wc = wid >> 2;   // q-band, f-half
    const int g = lane >> 2, t4 = lane & 3;  // fragment row, quad index
    const int b = blockIdx.y;
    const int causal = causality[0];

    const uint32_t* Q32  = (const uint32_t*)(smem + Q_OFF);
    const uint32_t* K32  = (const uint32_t*)(smem + K_OFF);
    const uint32_t* Vt32 = (const uint32_t*)(smem + VT_OFF);
    const uint32_t* Ph32 = (const uint32_t*)(smem + PH_OFF);
    float* den_s = (float*)(smem + DEN_OFF);

    const int ar0 = (16 * wr + g) * QKW;
    const int ar1 = (16 * wr + g + 8) * QKW;
    const int pr0 = (16 * wr + g) * VPW;
    const int pr1 = (16 * wr + g + 8) * VPW;

    auto stage_K = [&](int k0) {
        const __half* k = g_k + ((size_t)b * NS + k0) * NDK;
#pragma unroll
        for (int l = 0; l < 8; ++l) {
            int i = tid + l * 256;
            int row = i >> 5, c8 = (i & 31) << 3;
            uint32_t off = (uint32_t)(row * (QKW * 2) + c8) * 2;
            CP16(sb + K_OFF + off, k + (size_t)row * NDK + c8);
        }
    };
    auto stage_V = [&](int k0) {
        const __half* vh = g_vt + (size_t)b * NF * NS + k0;
#pragma unroll
        for (int l = 0; l < 8; ++l) {
            int i = tid + l * 256;
            int f = i >> 3, k8 = (i & 7) << 3;
            uint32_t off = (uint32_t)(f * (VPW * 2) + k8) * 2;
            CP16(sb + VT_OFF + off, vh + (size_t)f * NS + k8);
        }
    };

    for (int half = 0; half < 2; ++half) {
        const int qt = half ? (31 - (int)blockIdx.x) : (int)blockIdx.x;
        const int q0 = qt * 64;

        __syncthreads();  // previous half fully done before Q restage

        {
            const __half* q = g_q + ((size_t)b * NS + q0) * NDK;
#pragma unroll
            for (int l = 0; l < 8; ++l) {
                int i = tid + l * 256;
                int row = i >> 5, c8 = (i & 31) << 3;
                uint32_t off = (uint32_t)(row * (QKW * 2) + c8) * 2;
                *(uint4*)(smem + Q_OFF + off) = *(const uint4*)(q + (size_t)row * NDK + c8);
            }
        }

        float o[16][4];
#pragma unroll
        for (int j = 0; j < 16; ++j)
#pragma unroll
            for (int u = 0; u < 4; ++u) o[j][u] = 0.f;
        float denA = 0.f, denB = 0.f;

        const int kt0 = causal ? qt : 0;

        stage_K(kt0 * 64);
        stage_V(kt0 * 64);
        CP_COMMIT();

        const int q1 = q0 + 16 * wr + g;
        const int q2 = q1 + 8;
        const float* m1p = cmask + ((size_t)b * NS + q1) * NS;
        const float* m2p = cmask + ((size_t)b * NS + q2) * NS;

        for (int kt = kt0; kt < 32; ++kt) {
            const int k0 = kt * 64;

            // mask floats (overlaps in-flight cp.async); causal compares only
            // needed in the diagonal tile (kt == qt): for kt > qt, k >= q always.
            float m[4][4];
            {
                const int kbase = k0 + 32 * wc + 2 * t4;
#pragma unroll
                for (int j = 0; j < 4; ++j) {
                    int kg = kbase + 8 * j;
                    float2 m1 = *(const float2*)(m1p + kg);
                    float2 m2 = *(const float2*)(m2p + kg);
                    m[j][0] = m1.x; m[j][1] = m1.y;
                    m[j][2] = m2.x; m[j][3] = m2.y;
                }
                if (causal && kt == qt) {
#pragma unroll
                    for (int j = 0; j < 4; ++j) {
                        int kg = kbase + 8 * j;
                        if (kg     < q1) m[j][0] = 0.f;
                        if (kg + 1 < q1) m[j][1] = 0.f;
                        if (kg     < q2) m[j][2] = 0.f;
                        if (kg + 1 < q2) m[j][3] = 0.f;
                    }
                }
            }

            CP_WAIT_ALL();
            __syncthreads();  // K/V (and Q on first iter) visible

            // ---- Phase A: S = Q K^T (single fp16 term)
            float s[4][4];
#pragma unroll
            for (int j = 0; j < 4; ++j)
#pragma unroll
                for (int u = 0; u < 4; ++u) s[j][u] = 0.f;

#pragma unroll 4
            for (int ks = 0; ks < 16; ++ks) {
                const int kw = ks * 8 + t4;
                uint32_t a[4];
                a[0] = Q32[ar0 + kw];     a[1] = Q32[ar1 + kw];
                a[2] = Q32[ar0 + kw + 4]; a[3] = Q32[ar1 + kw + 4];
#pragma unroll
                for (int jp = 0; jp < 2; ++jp) {
                    const int br0 = (32 * wc + 16 * jp + g) * QKW;
                    const int br1 = (32 * wc + 16 * jp + 8 + g) * QKW;
                    uint32_t b0 = K32[br0 + kw], b1 = K32[br0 + kw + 4];
                    uint32_t b2 = K32[br1 + kw], b3 = K32[br1 + kw + 4];
                    mma_f16(s[2 * jp],     a, b0, b1);
                    mma_f16(s[2 * jp + 1], a, b2, b3);
                }
            }

            // ---- epilogue: p = 2^(min(s*EXPC, EXPMX)) * m; den; P fp16
            {
#pragma unroll
                for (int j = 0; j < 4; ++j) {
                    float p0 = ex2f(fminf(s[j][0] * EXPC, EXPMX)) * m[j][0];
                    float p1 = ex2f(fminf(s[j][1] * EXPC, EXPMX)) * m[j][1];
                    float p2 = ex2f(fminf(s[j][2] * EXPC, EXPMX)) * m[j][2];
                    float p3 = ex2f(fminf(s[j][3] * EXPC, EXPMX)) * m[j][3];
                    denA += p0 + p1;
                    denB += p2 + p3;
                    int col = 32 * wc + 2 * t4 + 8 * j;
                    uint32_t w1 = (uint32_t)((16 * wr + g) * VPW + (col >> 1));
                    uint32_t w2 = (uint32_t)((16 * wr + g + 8) * VPW + (col >> 1));
                    ((uint32_t*)(smem + PH_OFF))[w1] = pack2_f16(p0, p1);
                    ((uint32_t*)(smem + PH_OFF))[w2] = pack2_f16(p2, p3);
                }
            }
            __syncthreads();  // P visible; all warps done with K (phase A)

            // prefetch next tile's K — overlaps all of phase B
            if (kt + 1 < 32) { stage_K(k0 + 64); CP_COMMIT(); }

            // ---- Phase B: O += P V^T (single fp16 term)
#pragma unroll
            for (int ks = 0; ks < 4; ++ks) {
                const int kw = ks * 8 + t4;
                uint32_t a[4];
                a[0] = Ph32[pr0 + kw];     a[1] = Ph32[pr1 + kw];
                a[2] = Ph32[pr0 + kw + 4]; a[3] = Ph32[pr1 + kw + 4];
#pragma unroll
                for (int jp = 0; jp < 8; ++jp) {
                    const int vr0 = (128 * wc + 16 * jp + g) * VPW;
                    const int vr1 = (128 * wc + 16 * jp + 8 + g) * VPW;
                    uint32_t b0 = Vt32[vr0 + kw], b1 = Vt32[vr0 + kw + 4];
                    uint32_t b2 = Vt32[vr1 + kw], b3 = Vt32[vr1 + kw + 4];
                    mma_f16(o[2 * jp],     a, b0, b1);
                    mma_f16(o[2 * jp + 1], a, b2, b3);
                }
            }
            __syncthreads();  // all warps done with V (phase B) and P

            // prefetch next tile's V — overlaps next tile's mask loads
            if (kt + 1 < 32) { stage_V(k0 + 64); CP_COMMIT(); }
        }

        denA += __shfl_xor_sync(0xffffffffu, denA, 1);
        denA += __shfl_xor_sync(0xffffffffu, denA, 2);
        denB += __shfl_xor_sync(0xffffffffu, denB, 1);
        denB += __shfl_xor_sync(0xffffffffu, denB, 2);
        __syncthreads();
        if (t4 == 0) {
            den_s[wc * 64 + 16 * wr + g] = denA;
            den_s[wc * 64 + 16 * wr + g + 8] = denB;
        }
        __syncthreads();

        {
            const int q1row = 16 * wr + g;
            const float inv1 = 1.0f / (den_s[q1row] + den_s[64 + q1row]);
            const float inv2 = 1.0f / (den_s[q1row + 8] + den_s[64 + q1row + 8]);
            float* o1 = out + ((size_t)b * NS + q0 + q1row) * NF;
            float* o2 = out + ((size_t)b * NS + q0 + q1row + 8) * NF;
#pragma unroll
            for (int j2 = 0; j2 < 16; ++j2) {
                int f = 128 * wc + 8 * j2 + 2 * t4;
                float2 v1, v2;
                v1.x = o[j2][0] * inv1; v1.y = o[j2][1] * inv1;
                v2.x = o[j2][2] * inv2; v2.y = o[j2][3] * inv2;
                *(float2*)(o1 + f) = v1;
                *(float2*)(o2 + f) = v2;
            }
        }
    }
}

// ---------------------------------------------------------------------------
extern "C" void kernel_launch(void* const* d_in, const int* in_sizes, int n_in,
                              void* d_out, int out_size)
{
    const float* seq  = (const float*)d_in[0];
    const float* pos  = (const float*)d_in[1];
    const float* tim  = (const float*)d_in[2];
    const float* Wq   = (const float*)d_in[3];
    const float* Wk   = (const float*)d_in[4];
    const float* cm   = (const float*)d_in[5];
    const int*   caus = (const int*)d_in[6];
    float* out = (float*)d_out;

    cudaFuncSetAttribute(proj_mma, cudaFuncAttributeMaxDynamicSharedMemorySize, PSMEM);
    cudaFuncSetAttribute(attn_mma, cudaFuncAttributeMaxDynamicSharedMemorySize, ASMEM);

    dim3 gp(NB * NS / 128, NDK / 128, 2);   // (128, 2, 2) = 512 CTAs
    proj_mma<<<gp, 256, PSMEM>>>(seq, pos, tim, Wq, Wk);

    dim3 gv(NS / 32, NF / 32, NB);
    vsplit_kernel<<<gv, dim3(32, 8)>>>(seq);

    dim3 ga(16, NB);   // 128 CTAs, 33 key-tiles each (causal), 1 wave
    attn_mma<<<ga, 256, ASMEM>>>(cm, caus, out);
}

// round 17
// speedup vs baseline: 1.9444x; 1.0925x over previous
#include <cuda_runtime.h>
#include <cuda_bf16.h>
#include <cuda_fp16.h>
#include <cstdint>

#define NB 8
#define NS 2048
#define NF 256
#define NE 64
#define NDK 256
#define NIN 384

__device__ __forceinline__ void mma_f16(float d[4], const uint32_t a[4],
                                        uint32_t b0, uint32_t b1) {
    asm volatile(
        "mma.sync.aligned.m16n8k16.row.col.f32.f16.f16.f32 "
        "{%0,%1,%2,%3}, {%4,%5,%6,%7}, {%8,%9}, {%0,%1,%2,%3};"
        : "+f"(d[0]), "+f"(d[1]), "+f"(d[2]), "+f"(d[3])
        : "r"(a[0]), "r"(a[1]), "r"(a[2]), "r"(a[3]), "r"(b0), "r"(b1));
}

__device__ __forceinline__ float ex2f(float x) {
    float r;
    asm("ex2.approx.ftz.f32 %0, %1;" : "=f"(r) : "f"(x));
    return r;
}

__device__ __forceinline__ uint32_t pack2_f16(float a, float b) {
    __half2 h;
    h.x = __float2half_rn(a); h.y = __float2half_rn(b);
    return *(uint32_t*)&h;
}

__device__ __forceinline__ uint32_t smem_u32(const void* p) {
    uint32_t a;
    asm("{ .reg .u64 t; cvta.to.shared.u64 t, %1; cvt.u32.u64 %0, t; }"
        : "=r"(a) : "l"(p));
    return a;
}

#define CP16(dst, src) \
    asm volatile("cp.async.cg.shared.global [%0], [%1], 16;" \
                 :: "r"(dst), "l"(src))
#define CP_COMMIT()   asm volatile("cp.async.commit_group;" ::: "memory")
#define CP_WAIT_ALL() asm volatile("cp.async.wait_all;" ::: "memory")

// exp2 constants: p = 2^(s_raw * 0.0625 * log2e), clamp at 10*log2e
#define EXPC  0.0901684403f
#define EXPMX 14.4269504f

// ---------------------------------------------------------------------------
// Global scratch: Q/K single fp16, V^T single fp16
// ---------------------------------------------------------------------------
__device__ __half g_q[(size_t)NB * NS * NDK];
__device__ __half g_k[(size_t)NB * NS * NDK];
__device__ __half g_vt[(size_t)NB * NF * NS];   // [b][f][s]

// ---------------------------------------------------------------------------
// Kernel 1: Q/K projection, fp16 single-term HMMA (X single, W single),
// fp32 accumulate.  K chunk 64, smem 36KB -> 2 CTAs/SM.
// ---------------------------------------------------------------------------
#define XW      36
#define XH_OFF  0
#define WH_OFF  18432
#define PSMEM   36864

__global__ __launch_bounds__(256, 2) void proj_mma(
    const float* __restrict__ seq, const float* __restrict__ pos,
    const float* __restrict__ tim, const float* __restrict__ Wq,
    const float* __restrict__ Wk)
{
    extern __shared__ char smem[];
    const int tid = threadIdx.x, wid = tid >> 5, lane = tid & 31;
    const int wr = wid & 3, wc = wid >> 2;
    const int g = lane >> 2, t4 = lane & 3;
    const int m0 = blockIdx.x * 128, n0 = blockIdx.y * 128;
    const float* W = blockIdx.z ? Wk : Wq;
    __half* dst = blockIdx.z ? g_k : g_q;

    uint32_t* Xh = (uint32_t*)(smem + XH_OFF);
    uint32_t* Wh = (uint32_t*)(smem + WH_OFF);

    float acc[2][8][4];
#pragma unroll
    for (int mi = 0; mi < 2; ++mi)
#pragma unroll
        for (int jn = 0; jn < 8; ++jn)
#pragma unroll
            for (int u = 0; u < 4; ++u) acc[mi][jn][u] = 0.f;

    for (int ch = 0; ch < 6; ++ch) {
        const float* xsrc; int xw, xcol;
        if (ch < 4)      { xsrc = seq; xw = NF; xcol = ch * 64; }
        else if (ch < 5) { xsrc = pos; xw = NE; xcol = 0; }
        else             { xsrc = tim; xw = NE; xcol = 0; }
        const int wcol = ch * 64;

        __syncthreads();
#pragma unroll
        for (int l = 0; l < 8; ++l) {
            int i = tid + l * 256;
            int row = i >> 4, cc = (i & 15) * 4;
            float4 xv = *(const float4*)(xsrc + (size_t)(m0 + row) * xw + xcol + cc);
            int w = row * XW + (cc >> 1);
            *(uint2*)(Xh + w) = make_uint2(pack2_f16(xv.x, xv.y),
                                           pack2_f16(xv.z, xv.w));
            float4 wv = *(const float4*)(W + (size_t)(n0 + row) * NIN + wcol + cc);
            *(uint2*)(Wh + w) = make_uint2(pack2_f16(wv.x, wv.y),
                                           pack2_f16(wv.z, wv.w));
        }
        __syncthreads();

#pragma unroll
        for (int ks = 0; ks < 4; ++ks) {
            const int kw = ks * 8 + t4;
            uint32_t a[2][4];
#pragma unroll
            for (int mi = 0; mi < 2; ++mi) {
                int r0 = (32 * wr + 16 * mi + g) * XW, r1 = r0 + 8 * XW;
                a[mi][0] = Xh[r0 + kw];     a[mi][1] = Xh[r1 + kw];
                a[mi][2] = Xh[r0 + kw + 4]; a[mi][3] = Xh[r1 + kw + 4];
            }
#pragma unroll
            for (int jn = 0; jn < 8; ++jn) {
                int br = (64 * wc + 8 * jn + g) * XW;
                uint32_t b0 = Wh[br + kw], b1 = Wh[br + kw + 4];
#pragma unroll
                for (int mi = 0; mi < 2; ++mi)
                    mma_f16(acc[mi][jn], a[mi], b0, b1);
            }
        }
    }

#pragma unroll
    for (int mi = 0; mi < 2; ++mi) {
        int m1 = m0 + 32 * wr + 16 * mi + g;
        int m2 = m1 + 8;
#pragma unroll
        for (int jn = 0; jn < 8; ++jn) {
            int n = n0 + 64 * wc + 8 * jn + 2 * t4;
            *(uint32_t*)(dst + (size_t)m1 * NDK + n) =
                pack2_f16(acc[mi][jn][0], acc[mi][jn][1]);
            *(uint32_t*)(dst + (size_t)m2 * NDK + n) =
                pack2_f16(acc[mi][jn][2], acc[mi][jn][3]);
        }
    }
}

// ---------------------------------------------------------------------------
// Kernel 2: V = seq transpose -> fp16: g_vt[b][f][s]
// ---------------------------------------------------------------------------
__global__ __launch_bounds__(256) void vsplit_kernel(const float* __restrict__ seq)
{
    __shared__ float t[32][33];
    const int b = blockIdx.z, s0 = blockIdx.x * 32, f0 = blockIdx.y * 32;
    const int tx = threadIdx.x, ty = threadIdx.y;
#pragma unroll
    for (int r = 0; r < 4; ++r) {
        int sl = ty + r * 8;
        t[sl][tx] = seq[((size_t)b * NS + s0 + sl) * NF + f0 + tx];
    }
    __syncthreads();
#pragma unroll
    for (int r = 0; r < 4; ++r) {
        int fl = ty + r * 8;
        g_vt[((size_t)b * NF + f0 + fl) * NS + s0 + tx] = __float2half_rn(t[tx][fl]);
    }
}

// ---------------------------------------------------------------------------
// Kernel 3: fused attention, DOUBLE-BUFFERED K/V cp.async pipeline.
// Per tile: wait(data for kt) -> sync -> issue stage(kt+1, other buf)
// (overlaps ALL of tile kt's compute) -> QK^T -> softmax -> sync -> PV.
// ---------------------------------------------------------------------------
#define QKW      132
#define VPW      36
#define KBUF     33792
#define VBUF     36864
#define Q_OFF    0
#define K_OFF    33792     /* two buffers: 33792, 67584 */
#define V_OFF    101376    /* two buffers: 101376, 138240 */
#define PH_OFF   175104
#define DEN_OFF  184320
#define ASMEM    184832

__global__ __launch_bounds__(256, 1) void attn_mma(
    const float* __restrict__ cmask,
    const int*   __restrict__ causality,
    float* __restrict__ out)
{
    extern __shared__ char smem[];
    const uint32_t sb = smem_u32(smem);
    const int tid = threadIdx.x;
    const int wid = tid >> 5, lane = tid & 31;
    const int wr = wid & 3, wc = wid >> 2;   // q-band, f-half
    const int g = lane >> 2, t4 = lane & 3;  // fragment row, quad index
    const int b = blockIdx.y;
    const int causal = causality[0];

    const uint32_t* Q32  = (const uint32_t*)(smem + Q_OFF);
    const uint32_t* Ph32 = (const uint32_t*)(smem + PH_OFF);
    float* den_s = (float*)(smem + DEN_OFF);

    const int ar0 = (16 * wr + g) * QKW;
    const int ar1 = (16 * wr + g + 8) * QKW;
    const int pr0 = (16 * wr + g) * VPW;
    const int pr1 = (16 * wr + g + 8) * VPW;

    auto stage_K = [&](int k0, uint32_t koff) {
        const __half* k = g_k + ((size_t)b * NS + k0) * NDK;
#pragma unroll
        for (int l = 0; l < 8; ++l) {
            int i = tid + l * 256;
            int row = i >> 5, c8 = (i & 31) << 3;
            uint32_t off = (uint32_t)(row * (QKW * 2) + c8) * 2;
            CP16(sb + koff + off, k + (size_t)row * NDK + c8);
        }
    };
    auto stage_V = [&](int k0, uint32_t voff) {
        const __half* vh = g_vt + (size_t)b * NF * NS + k0;
#pragma unroll
        for (int l = 0; l < 8; ++l) {
            int i = tid + l * 256;
            int f = i >> 3, k8 = (i & 7) << 3;
            uint32_t off = (uint32_t)(f * (VPW * 2) + k8) * 2;
            CP16(sb + voff + off, vh + (size_t)f * NS + k8);
        }
    };

    for (int half = 0; half < 2; ++half) {
        const int qt = half ? (31 - (int)blockIdx.x) : (int)blockIdx.x;
        const int q0 = qt * 64;

        __syncthreads();  // previous half fully done before Q/buf0 restage

        {
            const __half* q = g_q + ((size_t)b * NS + q0) * NDK;
#pragma unroll
            for (int l = 0; l < 8; ++l) {
                int i = tid + l * 256;
                int row = i >> 5, c8 = (i & 31) << 3;
                uint32_t off = (uint32_t)(row * (QKW * 2) + c8) * 2;
                *(uint4*)(smem + Q_OFF + off) = *(const uint4*)(q + (size_t)row * NDK + c8);
            }
        }

        float o[16][4];
#pragma unroll
        for (int j = 0; j < 16; ++j)
#pragma unroll
            for (int u = 0; u < 4; ++u) o[j][u] = 0.f;
        float denA = 0.f, denB = 0.f;

        const int kt0 = causal ? qt : 0;

        stage_K(kt0 * 64, K_OFF);
        stage_V(kt0 * 64, V_OFF);
        CP_COMMIT();

        const int q1 = q0 + 16 * wr + g;
        const int q2 = q1 + 8;
        const float* m1p = cmask + ((size_t)b * NS + q1) * NS;
        const float* m2p = cmask + ((size_t)b * NS + q2) * NS;

        for (int kt = kt0; kt < 32; ++kt) {
            const int k0 = kt * 64;
            const int pb = (kt - kt0) & 1;
            const uint32_t* Kb = (const uint32_t*)(smem + K_OFF + pb * KBUF);
            const uint32_t* Vb = (const uint32_t*)(smem + V_OFF + pb * VBUF);

            // mask floats (overlap in-flight cp.async); causal compares only
            // in the diagonal tile (kt > qt implies k >= q automatically).
            float m[4][4];
            {
                const int kbase = k0 + 32 * wc + 2 * t4;
#pragma unroll
                for (int j = 0; j < 4; ++j) {
                    int kg = kbase + 8 * j;
                    float2 m1 = *(const float2*)(m1p + kg);
                    float2 m2 = *(const float2*)(m2p + kg);
                    m[j][0] = m1.x; m[j][1] = m1.y;
                    m[j][2] = m2.x; m[j][3] = m2.y;
                }
                if (causal && kt == qt) {
#pragma unroll
                    for (int j = 0; j < 4; ++j) {
                        int kg = kbase + 8 * j;
                        if (kg     < q1) m[j][0] = 0.f;
                        if (kg + 1 < q1) m[j][1] = 0.f;
                        if (kg     < q2) m[j][2] = 0.f;
                        if (kg + 1 < q2) m[j][3] = 0.f;
                    }
                }
            }

            CP_WAIT_ALL();      // tile kt's K/V landed (kt+1 not yet issued)
            __syncthreads();    // visible to all; prev tile's readers done

            // issue next tile's staging into the OTHER buffer — overlaps
            // this tile's entire compute (QK^T + softmax + PV).
            if (kt + 1 < 32) {
                stage_K(k0 + 64, K_OFF + (pb ^ 1) * KBUF);
                stage_V(k0 + 64, V_OFF + (pb ^ 1) * VBUF);
                CP_COMMIT();
            }

            // ---- Phase A: S = Q K^T (single fp16 term)
            float s[4][4];
#pragma unroll
            for (int j = 0; j < 4; ++j)
#pragma unroll
                for (int u = 0; u < 4; ++u) s[j][u] = 0.f;

#pragma unroll 4
            for (int ks = 0; ks < 16; ++ks) {
                const int kw = ks * 8 + t4;
                uint32_t a[4];
                a[0] = Q32[ar0 + kw];     a[1] = Q32[ar1 + kw];
                a[2] = Q32[ar0 + kw + 4]; a[3] = Q32[ar1 + kw + 4];
#pragma unroll
                for (int jp = 0; jp < 2; ++jp) {
                    const int br0 = (32 * wc + 16 * jp + g) * QKW;
                    const int br1 = (32 * wc + 16 * jp + 8 + g) * QKW;
                    uint32_t b0 = Kb[br0 + kw], b1 = Kb[br0 + kw + 4];
                    uint32_t b2 = Kb[br1 + kw], b3 = Kb[br1 + kw + 4];
                    mma_f16(s[2 * jp],     a, b0, b1);
                    mma_f16(s[2 * jp + 1], a, b2, b3);
                }
            }

            // ---- epilogue: p = 2^(min(s*EXPC, EXPMX)) * m; den; P fp16
            {
#pragma unroll
                for (int j = 0; j < 4; ++j) {
                    float p0 = ex2f(fminf(s[j][0] * EXPC, EXPMX)) * m[j][0];
                    float p1 = ex2f(fminf(s[j][1] * EXPC, EXPMX)) * m[j][1];
                    float p2 = ex2f(fminf(s[j][2] * EXPC, EXPMX)) * m[j][2];
                    float p3 = ex2f(fminf(s[j][3] * EXPC, EXPMX)) * m[j][3];
                    denA += p0 + p1;
                    denB += p2 + p3;
                    int col = 32 * wc + 2 * t4 + 8 * j;
                    uint32_t w1 = (uint32_t)((16 * wr + g) * VPW + (col >> 1));
                    uint32_t w2 = (uint32_t)((16 * wr + g + 8) * VPW + (col >> 1));
                    ((uint32_t*)(smem + PH_OFF))[w1] = pack2_f16(p0, p1);
                    ((uint32_t*)(smem + PH_OFF))[w2] = pack2_f16(p2, p3);
                }
            }
            __syncthreads();  // P visible across warps

            // ---- Phase B: O += P V^T (single fp16 term)
#pragma unroll
            for (int ks = 0; ks < 4; ++ks) {
                const int kw = ks * 8 + t4;
                uint32_t a[4];
                a[0] = Ph32[pr0 + kw];     a[1] = Ph32[pr1 + kw];
                a[2] = Ph32[pr0 + kw + 4]; a[3] = Ph32[pr1 + kw + 4];
#pragma unroll
                for (int jp = 0; jp < 8; ++jp) {
                    const int vr0 = (128 * wc + 16 * jp + g) * VPW;
                    const int vr1 = (128 * wc + 16 * jp + 8 + g) * VPW;
                    uint32_t b0 = Vb[vr0 + kw], b1 = Vb[vr0 + kw + 4];
                    uint32_t b2 = Vb[vr1 + kw], b3 = Vb[vr1 + kw + 4];
                    mma_f16(o[2 * jp],     a, b0, b1);
                    mma_f16(o[2 * jp + 1], a, b2, b3);
                }
            }
            // no trailing sync: next iteration's top sync guards P rewrite,
            // and staging targets the other buffer.
        }

        denA += __shfl_xor_sync(0xffffffffu, denA, 1);
        denA += __shfl_xor_sync(0xffffffffu, denA, 2);
        denB += __shfl_xor_sync(0xffffffffu, denB, 1);
        denB += __shfl_xor_sync(0xffffffffu, denB, 2);
        __syncthreads();  // last tile's P readers done before den_s write
        if (t4 == 0) {
            den_s[wc * 64 + 16 * wr + g] = denA;
            den_s[wc * 64 + 16 * wr + g + 8] = denB;
        }
        __syncthreads();

        {
            const int q1row = 16 * wr + g;
            const float inv1 = 1.0f / (den_s[q1row] + den_s[64 + q1row]);
            const float inv2 = 1.0f / (den_s[q1row + 8] + den_s[64 + q1row + 8]);
            float* o1 = out + ((size_t)b * NS + q0 + q1row) * NF;
            float* o2 = out + ((size_t)b * NS + q0 + q1row + 8) * NF;
#pragma unroll
            for (int j2 = 0; j2 < 16; ++j2) {
                int f = 128 * wc + 8 * j2 + 2 * t4;
                float2 v1, v2;
                v1.x = o[j2][0] * inv1; v1.y = o[j2][1] * inv1;
                v2.x = o[j2][2] * inv2; v2.y = o[j2][3] * inv2;
                *(float2*)(o1 + f) = v1;
                *(float2*)(o2 + f) = v2;
            }
        }
    }
}

// ---------------------------------------------------------------------------
extern "C" void kernel_launch(void* const* d_in, const int* in_sizes, int n_in,
                              void* d_out, int out_size)
{
    const float* seq  = (const float*)d_in[0];
    const float* pos  = (const float*)d_in[1];
    const float* tim  = (const float*)d_in[2];
    const float* Wq   = (const float*)d_in[3];
    const float* Wk   = (const float*)d_in[4];
    const float* cm   = (const float*)d_in[5];
    const int*   caus = (const int*)d_in[6];
    float* out = (float*)d_out;

    cudaFuncSetAttribute(proj_mma, cudaFuncAttributeMaxDynamicSharedMemorySize, PSMEM);
    cudaFuncSetAttribute(attn_mma, cudaFuncAttributeMaxDynamicSharedMemorySize, ASMEM);

    dim3 gp(NB * NS / 128, NDK / 128, 2);   // (128, 2, 2) = 512 CTAs
    proj_mma<<<gp, 256, PSMEM>>>(seq, pos, tim, Wq, Wk);

    dim3 gv(NS / 32, NF / 32, NB);
    vsplit_kernel<<<gv, dim3(32, 8)>>>(seq);

    dim3 ga(16, NB);   // 128 CTAs, 33 key-tiles each (causal), 1 wave
    attn_mma<<<ga, 256, ASMEM>>>(cm, caus, out);
}